// round 8
// baseline (speedup 1.0000x reference)
#include <cuda_runtime.h>
#include <cuda_bf16.h>
#include <stdint.h>
#include <math.h>

#define NHEADS 12
#define DH     64
#define LW     49
#define CCH    768
#define NWIN   2048
#define MROWS  (NWIN * LW)                 // 100352
#define XTOT   ((size_t)MROWS * CCH)

// ---------------- device-global split planes -------------------------------
__device__ __nv_bfloat16 g_sh[(size_t)MROWS * CCH];   // attention out hi
__device__ __nv_bfloat16 g_sl[(size_t)MROWS * CCH];   // attention out lo
__device__ __nv_bfloat16 g_wqh[12 * 4096], g_wkh[12 * 4096];
__device__ __nv_bfloat16 g_wvh[12 * 4096], g_wvl[12 * 4096];
__device__ __nv_bfloat16 g_woh[589824], g_wol[589824];

// ---------------- helpers ---------------------------------------------------
__device__ __forceinline__ void mma_bf16(float c[4], const uint32_t a[4],
                                         uint32_t b0, uint32_t b1) {
    asm volatile(
        "mma.sync.aligned.m16n8k16.row.col.f32.bf16.bf16.f32 "
        "{%0,%1,%2,%3},{%4,%5,%6,%7},{%8,%9},{%0,%1,%2,%3};\n"
        : "+f"(c[0]), "+f"(c[1]), "+f"(c[2]), "+f"(c[3])
        : "r"(a[0]), "r"(a[1]), "r"(a[2]), "r"(a[3]), "r"(b0), "r"(b1));
}

__device__ __forceinline__ void ldsm4(uint32_t r[4], uint32_t saddr) {
    asm volatile("ldmatrix.sync.aligned.m8n8.x4.shared.b16 {%0,%1,%2,%3},[%4];"
                 : "=r"(r[0]), "=r"(r[1]), "=r"(r[2]), "=r"(r[3]) : "r"(saddr));
}

__device__ __forceinline__ void ldsm4t(uint32_t r[4], uint32_t saddr) {
    asm volatile("ldmatrix.sync.aligned.m8n8.x4.trans.shared.b16 {%0,%1,%2,%3},[%4];"
                 : "=r"(r[0]), "=r"(r[1]), "=r"(r[2]), "=r"(r[3]) : "r"(saddr));
}

__device__ __forceinline__ void split_bf(float v, __nv_bfloat16& h, __nv_bfloat16& l) {
    h = __float2bfloat16(v);
    l = __float2bfloat16(v - __bfloat162float(h));
}

__device__ __forceinline__ uint32_t packbf(__nv_bfloat16 a, __nv_bfloat16 b) {
    __nv_bfloat162 t; t.x = a; t.y = b;
    return *reinterpret_cast<uint32_t*>(&t);
}

__device__ __forceinline__ void cpa16(uint32_t dst, const void* src) {
    asm volatile("cp.async.cg.shared.global [%0], [%1], 16;" :: "r"(dst), "l"(src));
}
__device__ __forceinline__ void cpa_commit() { asm volatile("cp.async.commit_group;"); }
template<int N> __device__ __forceinline__ void cpa_wait() {
    asm volatile("cp.async.wait_group %0;" :: "n"(N));
}

// ============================================================================
// Prep: weights only
// ============================================================================
__global__ void split_w_kernel(const float* __restrict__ Wq, const float* __restrict__ Wk,
                               const float* __restrict__ Wv, const float* __restrict__ Wo) {
    int np = 589824 / 2;
    for (int i = blockIdx.x * blockDim.x + threadIdx.x; i < np;
         i += gridDim.x * blockDim.x) {
        float2 v = ((const float2*)Wo)[i];
        __nv_bfloat16 h0, l0, h1, l1;
        split_bf(v.x, h0, l0); split_bf(v.y, h1, l1);
        ((uint32_t*)g_woh)[i] = packbf(h0, h1);
        ((uint32_t*)g_wol)[i] = packbf(l0, l1);
        if (i < 24576) {
            float2 q = ((const float2*)Wq)[i];
            ((uint32_t*)g_wqh)[i] = packbf(__float2bfloat16(q.x), __float2bfloat16(q.y));
            float2 k = ((const float2*)Wk)[i];
            ((uint32_t*)g_wkh)[i] = packbf(__float2bfloat16(k.x), __float2bfloat16(k.y));
            float2 w = ((const float2*)Wv)[i];
            split_bf(w.x, h0, l0); split_bf(w.y, h1, l1);
            ((uint32_t*)g_wvh)[i] = packbf(h0, h1);
            ((uint32_t*)g_wvl)[i] = packbf(l0, l1);
        }
    }
}

// ============================================================================
// Kernel A: per-(window, head) fused QKV projection + attention.
// Plane usage over time:
//   plane0/1: x hi/lo  -> Sc (fp32 scores)
//   plane2/3: Wq/Wk    -> V hi/lo (row-major)
//   plane4/5: Q/K      -> P hi/lo
//   plane6/7: Wv hi/lo (cp.async at entry)
// ============================================================================
#define STBF  72
#define PLANE (64 * STBF)
#define PLB   (PLANE * 2)
#define SMEMB (8 * PLB)
#define SCST  65                       // fp32 score-row stride (conflict-free)

__device__ __forceinline__ void gemm_pass(float acc[2][4][4], uint32_t aBase,
                                          uint32_t bBase, int mbase, int nbase,
                                          int lane) {
    const int r16 = lane & 15;
    const uint32_t kaq = (lane >> 4) * 16;
    #pragma unroll
    for (int kc = 0; kc < 4; ++kc) {
        uint32_t ka = kaq + kc * 32;
        uint32_t a0[4], a1[4], b0[4], b1[4];
        ldsm4(a0, aBase + (mbase + r16) * 144 + ka);
        ldsm4(a1, aBase + (mbase + 16 + r16) * 144 + ka);
        ldsm4(b0, bBase + (nbase + r16) * 144 + ka);
        ldsm4(b1, bBase + (nbase + 16 + r16) * 144 + ka);
        mma_bf16(acc[0][0], a0, b0[0], b0[2]);
        mma_bf16(acc[0][1], a0, b0[1], b0[3]);
        mma_bf16(acc[0][2], a0, b1[0], b1[2]);
        mma_bf16(acc[0][3], a0, b1[1], b1[3]);
        mma_bf16(acc[1][0], a1, b0[0], b0[2]);
        mma_bf16(acc[1][1], a1, b0[1], b0[3]);
        mma_bf16(acc[1][2], a1, b1[0], b1[2]);
        mma_bf16(acc[1][3], a1, b1[1], b1[3]);
    }
}

// A row-major, B row-major [k][n] loaded via ldmatrix.trans (for P @ V)
__device__ __forceinline__ void gemm_pass_tb(float acc[2][4][4], uint32_t aBase,
                                             uint32_t bBase, int mbase, int nbase,
                                             int lane) {
    const int r16 = lane & 15;
    const uint32_t kaq = (lane >> 4) * 16;
    const int krow = ((lane >> 4) << 3) + (lane & 7);   // 0..15 within k16 tile
    const int nch = ((lane >> 3) & 1) * 8;              // n sub-chunk 0 / 8
    #pragma unroll
    for (int kc = 0; kc < 4; ++kc) {
        uint32_t ka = kaq + kc * 32;
        uint32_t a0[4], a1[4], b0[4], b1[4];
        ldsm4(a0, aBase + (mbase + r16) * 144 + ka);
        ldsm4(a1, aBase + (mbase + 16 + r16) * 144 + ka);
        const uint32_t brow = bBase + (kc * 16 + krow) * 144;
        ldsm4t(b0, brow + (nbase + nch) * 2);
        ldsm4t(b1, brow + (nbase + 16 + nch) * 2);
        mma_bf16(acc[0][0], a0, b0[0], b0[2]);
        mma_bf16(acc[0][1], a0, b0[1], b0[3]);
        mma_bf16(acc[0][2], a0, b1[0], b1[2]);
        mma_bf16(acc[0][3], a0, b1[1], b1[3]);
        mma_bf16(acc[1][0], a1, b0[0], b0[2]);
        mma_bf16(acc[1][1], a1, b0[1], b0[3]);
        mma_bf16(acc[1][2], a1, b1[0], b1[2]);
        mma_bf16(acc[1][3], a1, b1[1], b1[3]);
    }
}

__global__ void __launch_bounds__(128, 3)
attn_kernel(const float* __restrict__ x)
{
    extern __shared__ __nv_bfloat16 sm[];
    __nv_bfloat16* xh = sm;                 // -> Sc
    __nv_bfloat16* xl = sm + PLANE;
    __nv_bfloat16* pA = sm + 2 * PLANE;     // Wq -> V hi
    __nv_bfloat16* pB = sm + 3 * PLANE;     // Wk -> V lo
    __nv_bfloat16* pQ = sm + 4 * PLANE;     // Q  -> P hi
    __nv_bfloat16* pK = sm + 5 * PLANE;     // K  -> P lo
    float* Sc = (float*)sm;                 // scores fp32 [64][65]

    const int tid = threadIdx.x, lane = tid & 31, wid = tid >> 5;
    const int warp_m = wid >> 1, warp_n = wid & 1;
    const int mbase = warp_m * 32, nbase = warp_n * 32;
    const int lr = lane >> 2, lc = lane & 3;

    const int h = blockIdx.x % NHEADS;
    const int n = blockIdx.x / NHEADS;
    const int b = n >> 6, hb = (n >> 3) & 7, wb = n & 7;

    const uint32_t sb = (uint32_t)__cvta_generic_to_shared(sm);
    const uint32_t sXH = sb, sXL = sb + PLB;
    const uint32_t sPA = sb + 2 * PLB, sPB = sb + 3 * PLB;
    const uint32_t sPQ = sb + 4 * PLB, sPK = sb + 5 * PLB;
    const uint32_t sWV = sb + 6 * PLB, sWVl = sb + 7 * PLB;

    // ---- cp.async ALL weights at entry (Wq->pA, Wk->pB, Wvh->p6, Wvl->p7) ----
    for (int q = tid; q < 2048; q += 128) {
        int pl = q >> 9;                   // 0..3
        int rem = q & 511, e = rem >> 3, ch = rem & 7;
        const __nv_bfloat16* src =
            (pl == 0 ? g_wqh : pl == 1 ? g_wkh : pl == 2 ? g_wvh : g_wvl)
            + h * 4096 + e * 64 + ch * 8;
        uint32_t dst = sb + (uint32_t)((pl < 2 ? (2 + pl) : (4 + pl)) * PLB)
                       + e * 144 + ch * 16;
        cpa16(dst, src);
    }
    cpa_commit();

    // ---- stage x: load fp32, split hi/lo inline (overlaps cp.async) ----
    for (int q = tid; q < 512; q += 128) {
        int l = q >> 3, ch = q & 7;
        uint4 hv = make_uint4(0, 0, 0, 0), lv = make_uint4(0, 0, 0, 0);
        if (l < LW) {
            int i = l / 7, j = l - i * 7;
            const float* src = x + (((size_t)(b * 56 + hb * 7 + i)) * 56 + (wb * 7 + j)) * CCH
                               + h * DH + ch * 8;
            float4 f0 = *(const float4*)src;
            float4 f1 = *(const float4*)(src + 4);
            __nv_bfloat16 h0, l0, h1, l1;
            split_bf(f0.x, h0, l0); split_bf(f0.y, h1, l1);
            hv.x = packbf(h0, h1); lv.x = packbf(l0, l1);
            split_bf(f0.z, h0, l0); split_bf(f0.w, h1, l1);
            hv.y = packbf(h0, h1); lv.y = packbf(l0, l1);
            split_bf(f1.x, h0, l0); split_bf(f1.y, h1, l1);
            hv.z = packbf(h0, h1); lv.z = packbf(l0, l1);
            split_bf(f1.z, h0, l0); split_bf(f1.w, h1, l1);
            hv.w = packbf(h0, h1); lv.w = packbf(l0, l1);
        }
        *(uint4*)(xh + l * STBF + ch * 8) = hv;
        *(uint4*)(xl + l * STBF + ch * 8) = lv;
    }
    cpa_wait<0>();
    __syncthreads();                        // barrier 1

    // ---- merged Q & K projections ----
    {
        float aq[2][4][4] = {}, ak[2][4][4] = {};
        const int r16 = lane & 15;
        const uint32_t kaq = (lane >> 4) * 16;
        #pragma unroll
        for (int kc = 0; kc < 4; ++kc) {
            uint32_t ka = kaq + kc * 32;
            uint32_t a0[4], a1[4], bq0[4], bq1[4], bk0[4], bk1[4];
            ldsm4(a0, sXH + (mbase + r16) * 144 + ka);
            ldsm4(a1, sXH + (mbase + 16 + r16) * 144 + ka);
            ldsm4(bq0, sPA + (nbase + r16) * 144 + ka);
            ldsm4(bq1, sPA + (nbase + 16 + r16) * 144 + ka);
            ldsm4(bk0, sPB + (nbase + r16) * 144 + ka);
            ldsm4(bk1, sPB + (nbase + 16 + r16) * 144 + ka);
            mma_bf16(aq[0][0], a0, bq0[0], bq0[2]);
            mma_bf16(aq[0][1], a0, bq0[1], bq0[3]);
            mma_bf16(aq[0][2], a0, bq1[0], bq1[2]);
            mma_bf16(aq[0][3], a0, bq1[1], bq1[3]);
            mma_bf16(aq[1][0], a1, bq0[0], bq0[2]);
            mma_bf16(aq[1][1], a1, bq0[1], bq0[3]);
            mma_bf16(aq[1][2], a1, bq1[0], bq1[2]);
            mma_bf16(aq[1][3], a1, bq1[1], bq1[3]);
            mma_bf16(ak[0][0], a0, bk0[0], bk0[2]);
            mma_bf16(ak[0][1], a0, bk0[1], bk0[3]);
            mma_bf16(ak[0][2], a0, bk1[0], bk1[2]);
            mma_bf16(ak[0][3], a0, bk1[1], bk1[3]);
            mma_bf16(ak[1][0], a1, bk0[0], bk0[2]);
            mma_bf16(ak[1][1], a1, bk0[1], bk0[3]);
            mma_bf16(ak[1][2], a1, bk1[0], bk1[2]);
            mma_bf16(ak[1][3], a1, bk1[1], bk1[3]);
        }
        uint32_t* OQ = (uint32_t*)pQ;
        uint32_t* OK = (uint32_t*)pK;
        #pragma unroll
        for (int f = 0; f < 2; ++f)
            #pragma unroll
            for (int g = 0; g < 4; ++g) {
                int r = mbase + 16 * f + lr;
                int w = r * 36 + (nbase + 8 * g) / 2 + lc;
                OQ[w] = packbf(__float2bfloat16(aq[f][g][0]), __float2bfloat16(aq[f][g][1]));
                OQ[w + 8 * 36] = packbf(__float2bfloat16(aq[f][g][2]), __float2bfloat16(aq[f][g][3]));
                OK[w] = packbf(__float2bfloat16(ak[f][g][0]), __float2bfloat16(ak[f][g][1]));
                OK[w + 8 * 36] = packbf(__float2bfloat16(ak[f][g][2]), __float2bfloat16(ak[f][g][3]));
            }
    }
    __syncthreads();                        // barrier 2 (pA/pB free after this)

    // ---- V = x @ Wv (3-term), output into pA/pB (row-major) ----
    {
        float acc[2][4][4] = {};
        gemm_pass(acc, sXH, sWV,  mbase, nbase, lane);
        gemm_pass(acc, sXH, sWVl, mbase, nbase, lane);
        gemm_pass(acc, sXL, sWV,  mbase, nbase, lane);
        uint32_t* OVH = (uint32_t*)pA;
        uint32_t* OVL = (uint32_t*)pB;
        #pragma unroll
        for (int f = 0; f < 2; ++f)
            #pragma unroll
            for (int g = 0; g < 4; ++g) {
                int r = mbase + 16 * f + lr;
                int w = r * 36 + (nbase + 8 * g) / 2 + lc;
                __nv_bfloat16 h0, l0, h1, l1;
                split_bf(acc[f][g][0], h0, l0);
                split_bf(acc[f][g][1], h1, l1);
                OVH[w] = packbf(h0, h1);
                OVL[w] = packbf(l0, l1);
                split_bf(acc[f][g][2], h0, l0);
                split_bf(acc[f][g][3], h1, l1);
                OVH[w + 8 * 36] = packbf(h0, h1);
                OVL[w + 8 * 36] = packbf(l0, l1);
            }
    }
    __syncthreads();                        // barrier 3 (xh/xl free after this)

    // ---- scores = Q @ K^T, scale + mask -> Sc ----
    {
        float acc[2][4][4] = {};
        gemm_pass(acc, sPQ, sPK, mbase, nbase, lane);
        #pragma unroll
        for (int f = 0; f < 2; ++f)
            #pragma unroll
            for (int g = 0; g < 4; ++g) {
                int r = mbase + 16 * f + lr;
                int c = nbase + 8 * g + 2 * lc;
                Sc[r * SCST + c]           = (c     < LW) ? acc[f][g][0] * 0.125f : -1e30f;
                Sc[r * SCST + c + 1]       = (c + 1 < LW) ? acc[f][g][1] * 0.125f : -1e30f;
                Sc[(r + 8) * SCST + c]     = (c     < LW) ? acc[f][g][2] * 0.125f : -1e30f;
                Sc[(r + 8) * SCST + c + 1] = (c + 1 < LW) ? acc[f][g][3] * 0.125f : -1e30f;
            }
    }
    __syncthreads();                        // barrier 4 (pQ/pK free after this)

    // ---- softmax: 2 threads per row, write P hi/lo into pQ/pK ----
    if (tid < 2 * LW) {
        const int r = tid >> 1, half = tid & 1;
        const unsigned msk = (tid < 96) ? 0xFFFFFFFFu : 0x3u;
        float* row = Sc + r * SCST;
        const int m0 = half ? 25 : 0, m1 = half ? LW : 25;
        float mx = -1e30f;
        #pragma unroll
        for (int m = m0; m < m1; ++m) mx = fmaxf(mx, row[m]);
        mx = fmaxf(mx, __shfl_xor_sync(msk, mx, 1));
        float s = 0.f;
        #pragma unroll
        for (int m = m0; m < m1; ++m) { float e = __expf(row[m] - mx); row[m] = e; s += e; }
        s += __shfl_xor_sync(msk, s, 1);
        float inv = 1.f / s;
        __syncwarp(msk);                   // make partner's exp stores visible
        uint32_t* ph = (uint32_t*)(pQ + r * STBF);
        uint32_t* pl = (uint32_t*)(pK + r * STBF);
        #pragma unroll
        for (int mw = half * 16; mw < half * 16 + 16; ++mw) {
            int mc = 2 * mw;
            float p0 = (mc     < LW) ? row[mc] * inv     : 0.f;
            float p1 = (mc + 1 < LW) ? row[mc + 1] * inv : 0.f;
            __nv_bfloat16 h0, l0, h1, l1;
            split_bf(p0, h0, l0);
            split_bf(p1, h1, l1);
            ph[mw] = packbf(h0, h1);
            pl[mw] = packbf(l0, l1);
        }
    }
    __syncthreads();                        // barrier 5

    // ---- out = P @ V (3-term, trans-B ldsm), store split bf16 ----
    {
        float acc[2][4][4] = {};
        gemm_pass_tb(acc, sPQ, sPA, mbase, nbase, lane);
        gemm_pass_tb(acc, sPQ, sPB, mbase, nbase, lane);
        gemm_pass_tb(acc, sPK, sPA, mbase, nbase, lane);
        #pragma unroll
        for (int f = 0; f < 2; ++f)
            #pragma unroll
            for (int g = 0; g < 4; ++g) {
                int r = mbase + 16 * f + lr;
                int c = nbase + 8 * g + 2 * lc;
                __nv_bfloat16 h0, l0, h1, l1;
                if (r < LW) {
                    size_t off = ((size_t)n * LW + r) * CCH + h * DH + c;
                    split_bf(acc[f][g][0], h0, l0);
                    split_bf(acc[f][g][1], h1, l1);
                    *(uint32_t*)(g_sh + off) = packbf(h0, h1);
                    *(uint32_t*)(g_sl + off) = packbf(l0, l1);
                }
                if (r + 8 < LW) {
                    size_t off = ((size_t)n * LW + r + 8) * CCH + h * DH + c;
                    split_bf(acc[f][g][2], h0, l0);
                    split_bf(acc[f][g][3], h1, l1);
                    *(uint32_t*)(g_sh + off) = packbf(h0, h1);
                    *(uint32_t*)(g_sl + off) = packbf(l0, l1);
                }
            }
    }
}

// ============================================================================
// Kernel B: y = S @ Wo^T + bo, bf16x3, 3-stage cp.async pipeline, SWIZZLED
// unpadded 64B rows. Block 128x64, BK=32, 256 threads. (unchanged)
// ============================================================================
#define PSTG 24576
#define QAH  0
#define QAL  8192
#define QBH  16384
#define QBL  20480
#define PROJ_SMEM (3 * PSTG)

__device__ __forceinline__ uint32_t swr(int row, int ch) {
    return (uint32_t)(row * 64 + ((ch ^ ((row >> 1) & 3)) << 4));
}

__device__ __forceinline__ void proj_stage(uint32_t sb, int s, int kt,
                                           int m_base, int n_base, int tid) {
    const uint32_t base = sb + s * PSTG;
    #pragma unroll
    for (int c = tid; c < 1024; c += 256) {
        int p = c >> 9, rem = c & 511, row = rem >> 2, ch = rem & 3;
        const __nv_bfloat16* src =
            (p ? g_sl : g_sh) + (size_t)(m_base + row) * CCH + kt + ch * 8;
        cpa16(base + (p ? QAL : QAH) + swr(row, ch), src);
    }
    #pragma unroll
    for (int c = tid; c < 512; c += 256) {
        int p = c >> 8, rem = c & 255, row = rem >> 2, ch = rem & 3;
        const __nv_bfloat16* src =
            (p ? g_wol : g_woh) + (size_t)(n_base + row) * CCH + kt + ch * 8;
        cpa16(base + (p ? QBL : QBH) + swr(row, ch), src);
    }
    cpa_commit();
}

__global__ void __launch_bounds__(256, 3)
proj_kernel(const float* __restrict__ bo, float* __restrict__ y)
{
    extern __shared__ __nv_bfloat16 psm[];
    const int tid = threadIdx.x, lane = tid & 31, wid = tid >> 5;
    const int warp_m = wid >> 1, warp_n = wid & 1;
    const int lr = lane >> 2, lc = lane & 3;
    const int n_base = (blockIdx.x % 12) * 64;
    const int m_base = (blockIdx.x / 12) * 128;
    const uint32_t sb = (uint32_t)__cvta_generic_to_shared(psm);
    const int r16 = lane & 15;
    const int colq = (lane >> 4);

    float acc[2][4][4] = {};

    auto compute = [&](int s) {
        const uint32_t base = sb + s * PSTG;
        const uint32_t aH = base + QAH, aL = base + QAL;
        const uint32_t bH = base + QBH, bL = base + QBL;
        #pragma unroll
        for (int kc = 0; kc < 2; ++kc) {
            const int ch = colq + kc * 2;
            const int ra0 = warp_m * 32 + r16, ra1 = ra0 + 16;
            const int rb0 = warp_n * 32 + r16, rb1 = rb0 + 16;
            uint32_t ah0[4], ah1[4], al0[4], al1[4], bh0[4], bh1[4], bl0[4], bl1[4];
            ldsm4(ah0, aH + swr(ra0, ch));
            ldsm4(ah1, aH + swr(ra1, ch));
            ldsm4(al0, aL + swr(ra0, ch));
            ldsm4(al1, aL + swr(ra1, ch));
            ldsm4(bh0, bH + swr(rb0, ch));
            ldsm4(bh1, bH + swr(rb1, ch));
            ldsm4(bl0, bL + swr(rb0, ch));
            ldsm4(bl1, bL + swr(rb1, ch));
            mma_bf16(acc[0][0], ah0, bh0[0], bh0[2]);
            mma_bf16(acc[0][0], ah0, bl0[0], bl0[2]);
            mma_bf16(acc[0][0], al0, bh0[0], bh0[2]);
            mma_bf16(acc[0][1], ah0, bh0[1], bh0[3]);
            mma_bf16(acc[0][1], ah0, bl0[1], bl0[3]);
            mma_bf16(acc[0][1], al0, bh0[1], bh0[3]);
            mma_bf16(acc[0][2], ah0, bh1[0], bh1[2]);
            mma_bf16(acc[0][2], ah0, bl1[0], bl1[2]);
            mma_bf16(acc[0][2], al0, bh1[0], bh1[2]);
            mma_bf16(acc[0][3], ah0, bh1[1], bh1[3]);
            mma_bf16(acc[0][3], ah0, bl1[1], bl1[3]);
            mma_bf16(acc[0][3], al0, bh1[1], bh1[3]);
            mma_bf16(acc[1][0], ah1, bh0[0], bh0[2]);
            mma_bf16(acc[1][0], ah1, bl0[0], bl0[2]);
            mma_bf16(acc[1][0], al1, bh0[0], bh0[2]);
            mma_bf16(acc[1][1], ah1, bh0[1], bh0[3]);
            mma_bf16(acc[1][1], ah1, bl0[1], bl0[3]);
            mma_bf16(acc[1][1], al1, bh0[1], bh0[3]);
            mma_bf16(acc[1][2], ah1, bh1[0], bh1[2]);
            mma_bf16(acc[1][2], ah1, bl1[0], bl1[2]);
            mma_bf16(acc[1][2], al1, bh1[0], bh1[2]);
            mma_bf16(acc[1][3], ah1, bh1[1], bh1[3]);
            mma_bf16(acc[1][3], ah1, bl1[1], bl1[3]);
            mma_bf16(acc[1][3], al1, bh1[1], bh1[3]);
        }
    };

    proj_stage(sb, 0, 0, m_base, n_base, tid);
    proj_stage(sb, 1, 32, m_base, n_base, tid);
    #pragma unroll 1
    for (int t = 0; t < 24; ++t) {
        if (t < 23) cpa_wait<1>(); else cpa_wait<0>();
        __syncthreads();
        compute(t % 3);
        if (t + 2 < 24) proj_stage(sb, (t + 2) % 3, (t + 2) * 32, m_base, n_base, tid);
    }

    #pragma unroll
    for (int g = 0; g < 4; ++g) {
        int c = n_base + warp_n * 32 + 8 * g + 2 * lc;
        float b0 = bo[c], b1 = bo[c + 1];
        #pragma unroll
        for (int f = 0; f < 2; ++f) {
            int r = m_base + warp_m * 32 + 16 * f + lr;
            *(float2*)&y[(size_t)r * CCH + c] =
                make_float2(acc[f][g][0] + b0, acc[f][g][1] + b1);
            *(float2*)&y[(size_t)(r + 8) * CCH + c] =
                make_float2(acc[f][g][2] + b0, acc[f][g][3] + b1);
        }
    }
}

// ============================================================================
extern "C" void kernel_launch(void* const* d_in, const int* in_sizes, int n_in,
                              void* d_out, int out_size)
{
    const float* x  = (const float*)d_in[0];
    const float* Wq = (const float*)d_in[1];
    const float* Wk = (const float*)d_in[2];
    const float* Wv = (const float*)d_in[3];
    const float* Wo = (const float*)d_in[4];
    const float* bo = (const float*)d_in[5];
    float* y = (float*)d_out;

    cudaFuncSetAttribute(attn_kernel, cudaFuncAttributeMaxDynamicSharedMemorySize, SMEMB);
    cudaFuncSetAttribute(proj_kernel, cudaFuncAttributeMaxDynamicSharedMemorySize, PROJ_SMEM);

    split_w_kernel<<<576, 256>>>(Wq, Wk, Wv, Wo);
    attn_kernel<<<NWIN * NHEADS, 128, SMEMB>>>(x);
    proj_kernel<<<784 * 12, 256, PROJ_SMEM>>>(bo, y);
}

// round 9
// speedup vs baseline: 1.3975x; 1.3975x over previous
#include <cuda_runtime.h>
#include <cuda_fp16.h>
#include <stdint.h>
#include <math.h>

#define NHEADS 12
#define DH     64
#define LW     49
#define CCH    768
#define NWIN   2048
#define MROWS  (NWIN * LW)                 // 100352

// ---------------- device-global fp16 planes --------------------------------
__device__ __half g_sh[(size_t)MROWS * CCH];          // attention out (hi only)
__device__ __half g_wqh[12 * 4096], g_wkh[12 * 4096], g_wvh[12 * 4096];
__device__ __half g_woh[589824], g_wol[589824];

// ---------------- helpers ---------------------------------------------------
__device__ __forceinline__ void mma_f16(float c[4], const uint32_t a[4],
                                        uint32_t b0, uint32_t b1) {
    asm volatile(
        "mma.sync.aligned.m16n8k16.row.col.f32.f16.f16.f32 "
        "{%0,%1,%2,%3},{%4,%5,%6,%7},{%8,%9},{%0,%1,%2,%3};\n"
        : "+f"(c[0]), "+f"(c[1]), "+f"(c[2]), "+f"(c[3])
        : "r"(a[0]), "r"(a[1]), "r"(a[2]), "r"(a[3]), "r"(b0), "r"(b1));
}

__device__ __forceinline__ void ldsm4(uint32_t r[4], uint32_t saddr) {
    asm volatile("ldmatrix.sync.aligned.m8n8.x4.shared.b16 {%0,%1,%2,%3},[%4];"
                 : "=r"(r[0]), "=r"(r[1]), "=r"(r[2]), "=r"(r[3]) : "r"(saddr));
}

__device__ __forceinline__ void ldsm4t(uint32_t r[4], uint32_t saddr) {
    asm volatile("ldmatrix.sync.aligned.m8n8.x4.trans.shared.b16 {%0,%1,%2,%3},[%4];"
                 : "=r"(r[0]), "=r"(r[1]), "=r"(r[2]), "=r"(r[3]) : "r"(saddr));
}

__device__ __forceinline__ void split_h(float v, __half& h, __half& l) {
    h = __float2half(v);
    l = __float2half(v - __half2float(h));
}

__device__ __forceinline__ uint32_t packh(__half a, __half b) {
    __half2 t; t.x = a; t.y = b;
    return *reinterpret_cast<uint32_t*>(&t);
}

__device__ __forceinline__ void cpa16(uint32_t dst, const void* src) {
    asm volatile("cp.async.cg.shared.global [%0], [%1], 16;" :: "r"(dst), "l"(src));
}
__device__ __forceinline__ void cpa_commit() { asm volatile("cp.async.commit_group;"); }
template<int N> __device__ __forceinline__ void cpa_wait() {
    asm volatile("cp.async.wait_group %0;" :: "n"(N));
}

// ============================================================================
// Prep: weights. Wq/Wk/Wv hi-only fp16; Wo split hi/lo fp16.
// ============================================================================
__global__ void split_w_kernel(const float* __restrict__ Wq, const float* __restrict__ Wk,
                               const float* __restrict__ Wv, const float* __restrict__ Wo) {
    int np = 589824 / 2;
    for (int i = blockIdx.x * blockDim.x + threadIdx.x; i < np;
         i += gridDim.x * blockDim.x) {
        float2 v = ((const float2*)Wo)[i];
        __half h0, l0, h1, l1;
        split_h(v.x, h0, l0); split_h(v.y, h1, l1);
        ((uint32_t*)g_woh)[i] = packh(h0, h1);
        ((uint32_t*)g_wol)[i] = packh(l0, l1);
        if (i < 24576) {
            float2 q = ((const float2*)Wq)[i];
            ((uint32_t*)g_wqh)[i] = packh(__float2half(q.x), __float2half(q.y));
            float2 k = ((const float2*)Wk)[i];
            ((uint32_t*)g_wkh)[i] = packh(__float2half(k.x), __float2half(k.y));
            float2 w = ((const float2*)Wv)[i];
            ((uint32_t*)g_wvh)[i] = packh(__float2half(w.x), __float2half(w.y));
        }
    }
}

// ============================================================================
// Kernel A: per-(window, head) fused QKV projection + attention, fp16.
// Planes: 0/1 x hi/lo -> Sc;  2 Wq -> V;  3 Wk (free after QK);
//         4 Q -> P hi;  5 K -> P lo;  6 Wv (hi only).
// ============================================================================
#define STBF  72
#define PLANE (64 * STBF)
#define PLB   (PLANE * 2)
#define SMEMB (7 * PLB)                // 64512 B
#define SCST  65

__device__ __forceinline__ void gemm_pass(float acc[2][4][4], uint32_t aBase,
                                          uint32_t bBase, int mbase, int nbase,
                                          int lane) {
    const int r16 = lane & 15;
    const uint32_t kaq = (lane >> 4) * 16;
    #pragma unroll
    for (int kc = 0; kc < 4; ++kc) {
        uint32_t ka = kaq + kc * 32;
        uint32_t a0[4], a1[4], b0[4], b1[4];
        ldsm4(a0, aBase + (mbase + r16) * 144 + ka);
        ldsm4(a1, aBase + (mbase + 16 + r16) * 144 + ka);
        ldsm4(b0, bBase + (nbase + r16) * 144 + ka);
        ldsm4(b1, bBase + (nbase + 16 + r16) * 144 + ka);
        mma_f16(acc[0][0], a0, b0[0], b0[2]);
        mma_f16(acc[0][1], a0, b0[1], b0[3]);
        mma_f16(acc[0][2], a0, b1[0], b1[2]);
        mma_f16(acc[0][3], a0, b1[1], b1[3]);
        mma_f16(acc[1][0], a1, b0[0], b0[2]);
        mma_f16(acc[1][1], a1, b0[1], b0[3]);
        mma_f16(acc[1][2], a1, b1[0], b1[2]);
        mma_f16(acc[1][3], a1, b1[1], b1[3]);
    }
}

// A row-major, B row-major [k][n] via ldmatrix.trans (for P @ V)
__device__ __forceinline__ void gemm_pass_tb(float acc[2][4][4], uint32_t aBase,
                                             uint32_t bBase, int mbase, int nbase,
                                             int lane) {
    const int r16 = lane & 15;
    const uint32_t kaq = (lane >> 4) * 16;
    const int krow = ((lane >> 4) << 3) + (lane & 7);
    const int nch = ((lane >> 3) & 1) * 8;
    #pragma unroll
    for (int kc = 0; kc < 4; ++kc) {
        uint32_t ka = kaq + kc * 32;
        uint32_t a0[4], a1[4], b0[4], b1[4];
        ldsm4(a0, aBase + (mbase + r16) * 144 + ka);
        ldsm4(a1, aBase + (mbase + 16 + r16) * 144 + ka);
        const uint32_t brow = bBase + (kc * 16 + krow) * 144;
        ldsm4t(b0, brow + (nbase + nch) * 2);
        ldsm4t(b1, brow + (nbase + 16 + nch) * 2);
        mma_f16(acc[0][0], a0, b0[0], b0[2]);
        mma_f16(acc[0][1], a0, b0[1], b0[3]);
        mma_f16(acc[0][2], a0, b1[0], b1[2]);
        mma_f16(acc[0][3], a0, b1[1], b1[3]);
        mma_f16(acc[1][0], a1, b0[0], b0[2]);
        mma_f16(acc[1][1], a1, b0[1], b0[3]);
        mma_f16(acc[1][2], a1, b1[0], b1[2]);
        mma_f16(acc[1][3], a1, b1[1], b1[3]);
    }
}

__global__ void __launch_bounds__(128, 3)
attn_kernel(const float* __restrict__ x)
{
    extern __shared__ __half sm[];
    __half* xh = sm;                 // -> Sc
    __half* xl = sm + PLANE;
    __half* pA = sm + 2 * PLANE;     // Wq -> V (row-major, hi only)
    __half* pB = sm + 3 * PLANE;     // Wk
    __half* pQ = sm + 4 * PLANE;     // Q -> P hi
    __half* pK = sm + 5 * PLANE;     // K -> P lo
    float* Sc = (float*)sm;          // scores fp32 [64][65]

    const int tid = threadIdx.x, lane = tid & 31, wid = tid >> 5;
    const int warp_m = wid >> 1, warp_n = wid & 1;
    const int mbase = warp_m * 32, nbase = warp_n * 32;
    const int lr = lane >> 2, lc = lane & 3;

    const int h = blockIdx.x % NHEADS;
    const int n = blockIdx.x / NHEADS;
    const int b = n >> 6, hb = (n >> 3) & 7, wb = n & 7;

    const uint32_t sb = (uint32_t)__cvta_generic_to_shared(sm);
    const uint32_t sXH = sb, sXL = sb + PLB;
    const uint32_t sPA = sb + 2 * PLB, sPB = sb + 3 * PLB;
    const uint32_t sPQ = sb + 4 * PLB, sPK = sb + 5 * PLB;
    const uint32_t sWV = sb + 6 * PLB;

    // ---- cp.async weights at entry (Wq->pA, Wk->pB, Wv->plane6) ----
    for (int q = tid; q < 1536; q += 128) {
        int pl = q >> 9;                   // 0..2
        int rem = q & 511, e = rem >> 3, ch = rem & 7;
        const __half* src = (pl == 0 ? g_wqh : pl == 1 ? g_wkh : g_wvh)
                            + h * 4096 + e * 64 + ch * 8;
        uint32_t dst = sb + (uint32_t)((pl < 2 ? (2 + pl) : 6) * PLB)
                       + e * 144 + ch * 16;
        cpa16(dst, src);
    }
    cpa_commit();

    // ---- stage x: fp32 loads, split fp16 hi/lo inline ----
    for (int q = tid; q < 512; q += 128) {
        int l = q >> 3, ch = q & 7;
        uint4 hv = make_uint4(0, 0, 0, 0), lv = make_uint4(0, 0, 0, 0);
        if (l < LW) {
            int i = l / 7, j = l - i * 7;
            const float* src = x + (((size_t)(b * 56 + hb * 7 + i)) * 56 + (wb * 7 + j)) * CCH
                               + h * DH + ch * 8;
            float4 f0 = *(const float4*)src;
            float4 f1 = *(const float4*)(src + 4);
            __half h0, l0, h1, l1;
            split_h(f0.x, h0, l0); split_h(f0.y, h1, l1);
            hv.x = packh(h0, h1); lv.x = packh(l0, l1);
            split_h(f0.z, h0, l0); split_h(f0.w, h1, l1);
            hv.y = packh(h0, h1); lv.y = packh(l0, l1);
            split_h(f1.x, h0, l0); split_h(f1.y, h1, l1);
            hv.z = packh(h0, h1); lv.z = packh(l0, l1);
            split_h(f1.z, h0, l0); split_h(f1.w, h1, l1);
            hv.w = packh(h0, h1); lv.w = packh(l0, l1);
        }
        *(uint4*)(xh + l * STBF + ch * 8) = hv;
        *(uint4*)(xl + l * STBF + ch * 8) = lv;
    }
    cpa_wait<0>();
    __syncthreads();

    // ---- merged Q & K projections (hi-only, 1 pass each, shared A frags) ----
    {
        float aq[2][4][4] = {}, ak[2][4][4] = {};
        const int r16 = lane & 15;
        const uint32_t kaq = (lane >> 4) * 16;
        #pragma unroll
        for (int kc = 0; kc < 4; ++kc) {
            uint32_t ka = kaq + kc * 32;
            uint32_t a0[4], a1[4], bq0[4], bq1[4], bk0[4], bk1[4];
            ldsm4(a0, sXH + (mbase + r16) * 144 + ka);
            ldsm4(a1, sXH + (mbase + 16 + r16) * 144 + ka);
            ldsm4(bq0, sPA + (nbase + r16) * 144 + ka);
            ldsm4(bq1, sPA + (nbase + 16 + r16) * 144 + ka);
            ldsm4(bk0, sPB + (nbase + r16) * 144 + ka);
            ldsm4(bk1, sPB + (nbase + 16 + r16) * 144 + ka);
            mma_f16(aq[0][0], a0, bq0[0], bq0[2]);
            mma_f16(aq[0][1], a0, bq0[1], bq0[3]);
            mma_f16(aq[0][2], a0, bq1[0], bq1[2]);
            mma_f16(aq[0][3], a0, bq1[1], bq1[3]);
            mma_f16(aq[1][0], a1, bq0[0], bq0[2]);
            mma_f16(aq[1][1], a1, bq0[1], bq0[3]);
            mma_f16(aq[1][2], a1, bq1[0], bq1[2]);
            mma_f16(aq[1][3], a1, bq1[1], bq1[3]);
            mma_f16(ak[0][0], a0, bk0[0], bk0[2]);
            mma_f16(ak[0][1], a0, bk0[1], bk0[3]);
            mma_f16(ak[0][2], a0, bk1[0], bk1[2]);
            mma_f16(ak[0][3], a0, bk1[1], bk1[3]);
            mma_f16(ak[1][0], a1, bk0[0], bk0[2]);
            mma_f16(ak[1][1], a1, bk0[1], bk0[3]);
            mma_f16(ak[1][2], a1, bk1[0], bk1[2]);
            mma_f16(ak[1][3], a1, bk1[1], bk1[3]);
        }
        uint32_t* OQ = (uint32_t*)pQ;
        uint32_t* OK = (uint32_t*)pK;
        #pragma unroll
        for (int f = 0; f < 2; ++f)
            #pragma unroll
            for (int g = 0; g < 4; ++g) {
                int r = mbase + 16 * f + lr;
                int w = r * 36 + (nbase + 8 * g) / 2 + lc;
                OQ[w] = packh(__float2half(aq[f][g][0]), __float2half(aq[f][g][1]));
                OQ[w + 8 * 36] = packh(__float2half(aq[f][g][2]), __float2half(aq[f][g][3]));
                OK[w] = packh(__float2half(ak[f][g][0]), __float2half(ak[f][g][1]));
                OK[w + 8 * 36] = packh(__float2half(ak[f][g][2]), __float2half(ak[f][g][3]));
            }
    }
    __syncthreads();                        // pA/pB free after this

    // ---- V = x @ Wv (2-term: xh*W + xl*W), store hi-only row-major in pA ----
    {
        float acc[2][4][4] = {};
        gemm_pass(acc, sXH, sWV, mbase, nbase, lane);
        gemm_pass(acc, sXL, sWV, mbase, nbase, lane);
        uint32_t* OV = (uint32_t*)pA;
        #pragma unroll
        for (int f = 0; f < 2; ++f)
            #pragma unroll
            for (int g = 0; g < 4; ++g) {
                int r = mbase + 16 * f + lr;
                int w = r * 36 + (nbase + 8 * g) / 2 + lc;
                OV[w] = packh(__float2half(acc[f][g][0]), __float2half(acc[f][g][1]));
                OV[w + 8 * 36] = packh(__float2half(acc[f][g][2]), __float2half(acc[f][g][3]));
            }
    }
    __syncthreads();                        // xh/xl free after this

    // ---- scores = Q @ K^T, scale + mask -> Sc ----
    {
        float acc[2][4][4] = {};
        gemm_pass(acc, sPQ, sPK, mbase, nbase, lane);
        #pragma unroll
        for (int f = 0; f < 2; ++f)
            #pragma unroll
            for (int g = 0; g < 4; ++g) {
                int r = mbase + 16 * f + lr;
                int c = nbase + 8 * g + 2 * lc;
                Sc[r * SCST + c]           = (c     < LW) ? acc[f][g][0] * 0.125f : -1e30f;
                Sc[r * SCST + c + 1]       = (c + 1 < LW) ? acc[f][g][1] * 0.125f : -1e30f;
                Sc[(r + 8) * SCST + c]     = (c     < LW) ? acc[f][g][2] * 0.125f : -1e30f;
                Sc[(r + 8) * SCST + c + 1] = (c + 1 < LW) ? acc[f][g][3] * 0.125f : -1e30f;
            }
    }
    __syncthreads();                        // pQ/pK free after this

    // ---- softmax: 2 threads per row, write P hi/lo into pQ/pK ----
    if (tid < 2 * LW) {
        const int r = tid >> 1, half = tid & 1;
        const unsigned msk = (tid < 96) ? 0xFFFFFFFFu : 0x3u;
        float* row = Sc + r * SCST;
        const int m0 = half ? 25 : 0, m1 = half ? LW : 25;
        float mx = -1e30f;
        #pragma unroll
        for (int m = m0; m < m1; ++m) mx = fmaxf(mx, row[m]);
        mx = fmaxf(mx, __shfl_xor_sync(msk, mx, 1));
        float s = 0.f;
        #pragma unroll
        for (int m = m0; m < m1; ++m) { float e = __expf(row[m] - mx); row[m] = e; s += e; }
        s += __shfl_xor_sync(msk, s, 1);
        float inv = 1.f / s;
        __syncwarp(msk);
        uint32_t* ph = (uint32_t*)(pQ + r * STBF);
        uint32_t* pl = (uint32_t*)(pK + r * STBF);
        #pragma unroll
        for (int mw = half * 16; mw < half * 16 + 16; ++mw) {
            int mc = 2 * mw;
            float p0 = (mc     < LW) ? row[mc] * inv     : 0.f;
            float p1 = (mc + 1 < LW) ? row[mc + 1] * inv : 0.f;
            __half h0, l0, h1, l1;
            split_h(p0, h0, l0);
            split_h(p1, h1, l1);
            ph[mw] = packh(h0, h1);
            pl[mw] = packh(l0, l1);
        }
    }
    __syncthreads();

    // ---- out = P @ V (2-term: Ph*V + Pl*V), store fp16 hi-only to g_sh ----
    {
        float acc[2][4][4] = {};
        gemm_pass_tb(acc, sPQ, sPA, mbase, nbase, lane);
        gemm_pass_tb(acc, sPK, sPA, mbase, nbase, lane);
        #pragma unroll
        for (int f = 0; f < 2; ++f)
            #pragma unroll
            for (int g = 0; g < 4; ++g) {
                int r = mbase + 16 * f + lr;
                int c = nbase + 8 * g + 2 * lc;
                if (r < LW) {
                    size_t off = ((size_t)n * LW + r) * CCH + h * DH + c;
                    *(uint32_t*)(g_sh + off) =
                        packh(__float2half(acc[f][g][0]), __float2half(acc[f][g][1]));
                }
                if (r + 8 < LW) {
                    size_t off = ((size_t)n * LW + r + 8) * CCH + h * DH + c;
                    *(uint32_t*)(g_sh + off) =
                        packh(__float2half(acc[f][g][2]), __float2half(acc[f][g][3]));
                }
            }
    }
}

// ============================================================================
// Kernel B: y = S @ Wo^T + bo, fp16 2-term (A hi-only, B hi+lo).
// 3-stage cp.async pipeline, swizzled 64B rows, 128x64 block, BK=32.
// ============================================================================
#define PSTG 16384                     // bytes per stage (A 8192, Bh 4096, Bl 4096)
#define QA   0
#define QBH  8192
#define QBL  12288
#define PROJ_SMEM (3 * PSTG)           // 49152 B

__device__ __forceinline__ uint32_t swr(int row, int ch) {
    return (uint32_t)(row * 64 + ((ch ^ ((row >> 1) & 3)) << 4));
}

__device__ __forceinline__ void proj_stage(uint32_t sb, int s, int kt,
                                           int m_base, int n_base, int tid) {
    const uint32_t base = sb + s * PSTG;
    #pragma unroll
    for (int c = tid; c < 512; c += 256) {         // A: 128 rows x 4 chunks
        int row = c >> 2, ch = c & 3;
        cpa16(base + QA + swr(row, ch),
              g_sh + (size_t)(m_base + row) * CCH + kt + ch * 8);
    }
    #pragma unroll
    for (int c = tid; c < 512; c += 256) {         // B hi/lo: 64 rows x 4 chunks
        int p = c >> 8, rem = c & 255, row = rem >> 2, ch = rem & 3;
        const __half* src =
            (p ? g_wol : g_woh) + (size_t)(n_base + row) * CCH + kt + ch * 8;
        cpa16(base + (p ? QBL : QBH) + swr(row, ch), src);
    }
    cpa_commit();
}

__global__ void __launch_bounds__(256, 3)
proj_kernel(const float* __restrict__ bo, float* __restrict__ y)
{
    extern __shared__ __half psm[];
    const int tid = threadIdx.x, lane = tid & 31, wid = tid >> 5;
    const int warp_m = wid >> 1, warp_n = wid & 1;
    const int lr = lane >> 2, lc = lane & 3;
    const int n_base = (blockIdx.x % 12) * 64;
    const int m_base = (blockIdx.x / 12) * 128;
    const uint32_t sb = (uint32_t)__cvta_generic_to_shared(psm);
    const int r16 = lane & 15;
    const int colq = (lane >> 4);

    float acc[2][4][4] = {};

    auto compute = [&](int s) {
        const uint32_t base = sb + s * PSTG;
        const uint32_t aB = base + QA;
        const uint32_t bH = base + QBH, bL = base + QBL;
        #pragma unroll
        for (int kc = 0; kc < 2; ++kc) {
            const int ch = colq + kc * 2;
            const int ra0 = warp_m * 32 + r16, ra1 = ra0 + 16;
            const int rb0 = warp_n * 32 + r16, rb1 = rb0 + 16;
            uint32_t a0[4], a1[4], bh0[4], bh1[4], bl0[4], bl1[4];
            ldsm4(a0, aB + swr(ra0, ch));
            ldsm4(a1, aB + swr(ra1, ch));
            ldsm4(bh0, bH + swr(rb0, ch));
            ldsm4(bh1, bH + swr(rb1, ch));
            ldsm4(bl0, bL + swr(rb0, ch));
            ldsm4(bl1, bL + swr(rb1, ch));
            mma_f16(acc[0][0], a0, bh0[0], bh0[2]);
            mma_f16(acc[0][0], a0, bl0[0], bl0[2]);
            mma_f16(acc[0][1], a0, bh0[1], bh0[3]);
            mma_f16(acc[0][1], a0, bl0[1], bl0[3]);
            mma_f16(acc[0][2], a0, bh1[0], bh1[2]);
            mma_f16(acc[0][2], a0, bl1[0], bl1[2]);
            mma_f16(acc[0][3], a0, bh1[1], bh1[3]);
            mma_f16(acc[0][3], a0, bl1[1], bl1[3]);
            mma_f16(acc[1][0], a1, bh0[0], bh0[2]);
            mma_f16(acc[1][0], a1, bl0[0], bl0[2]);
            mma_f16(acc[1][1], a1, bh0[1], bh0[3]);
            mma_f16(acc[1][1], a1, bl0[1], bl0[3]);
            mma_f16(acc[1][2], a1, bh1[0], bh1[2]);
            mma_f16(acc[1][2], a1, bl1[0], bl1[2]);
            mma_f16(acc[1][3], a1, bh1[1], bh1[3]);
            mma_f16(acc[1][3], a1, bl1[1], bl1[3]);
        }
    };

    proj_stage(sb, 0, 0, m_base, n_base, tid);
    proj_stage(sb, 1, 32, m_base, n_base, tid);
    #pragma unroll 1
    for (int t = 0; t < 24; ++t) {
        if (t < 23) cpa_wait<1>(); else cpa_wait<0>();
        __syncthreads();
        compute(t % 3);
        if (t + 2 < 24) proj_stage(sb, (t + 2) % 3, (t + 2) * 32, m_base, n_base, tid);
    }

    #pragma unroll
    for (int g = 0; g < 4; ++g) {
        int c = n_base + warp_n * 32 + 8 * g + 2 * lc;
        float b0 = bo[c], b1 = bo[c + 1];
        #pragma unroll
        for (int f = 0; f < 2; ++f) {
            int r = m_base + warp_m * 32 + 16 * f + lr;
            *(float2*)&y[(size_t)r * CCH + c] =
                make_float2(acc[f][g][0] + b0, acc[f][g][1] + b1);
            *(float2*)&y[(size_t)(r + 8) * CCH + c] =
                make_float2(acc[f][g][2] + b0, acc[f][g][3] + b1);
        }
    }
}

// ============================================================================
extern "C" void kernel_launch(void* const* d_in, const int* in_sizes, int n_in,
                              void* d_out, int out_size)
{
    const float* x  = (const float*)d_in[0];
    const float* Wq = (const float*)d_in[1];
    const float* Wk = (const float*)d_in[2];
    const float* Wv = (const float*)d_in[3];
    const float* Wo = (const float*)d_in[4];
    const float* bo = (const float*)d_in[5];
    float* y = (float*)d_out;

    cudaFuncSetAttribute(attn_kernel, cudaFuncAttributeMaxDynamicSharedMemorySize, SMEMB);
    cudaFuncSetAttribute(proj_kernel, cudaFuncAttributeMaxDynamicSharedMemorySize, PROJ_SMEM);

    split_w_kernel<<<576, 256>>>(Wq, Wk, Wv, Wo);
    attn_kernel<<<NWIN * NHEADS, 128, SMEMB>>>(x);
    proj_kernel<<<784 * 12, 256, PROJ_SMEM>>>(bo, y);
}

// round 10
// speedup vs baseline: 1.8280x; 1.3081x over previous
#include <cuda_runtime.h>
#include <cuda_fp16.h>
#include <stdint.h>
#include <math.h>

#define NHEADS 12
#define DH     64
#define LW     49
#define CCH    768
#define NWIN   2048
#define MROWS  (NWIN * LW)                 // 100352

// ---------------- device-global fp16 planes --------------------------------
__device__ __half g_sh[(size_t)MROWS * CCH];          // attention out
__device__ __half g_wqh[12 * 4096], g_wkh[12 * 4096], g_wvh[12 * 4096];
__device__ __half g_woh[589824];

// ---------------- helpers ---------------------------------------------------
__device__ __forceinline__ void mma_f16(float c[4], const uint32_t a[4],
                                        uint32_t b0, uint32_t b1) {
    asm volatile(
        "mma.sync.aligned.m16n8k16.row.col.f32.f16.f16.f32 "
        "{%0,%1,%2,%3},{%4,%5,%6,%7},{%8,%9},{%0,%1,%2,%3};\n"
        : "+f"(c[0]), "+f"(c[1]), "+f"(c[2]), "+f"(c[3])
        : "r"(a[0]), "r"(a[1]), "r"(a[2]), "r"(a[3]), "r"(b0), "r"(b1));
}

__device__ __forceinline__ void ldsm4(uint32_t r[4], uint32_t saddr) {
    asm volatile("ldmatrix.sync.aligned.m8n8.x4.shared.b16 {%0,%1,%2,%3},[%4];"
                 : "=r"(r[0]), "=r"(r[1]), "=r"(r[2]), "=r"(r[3]) : "r"(saddr));
}

__device__ __forceinline__ void ldsm4t(uint32_t r[4], uint32_t saddr) {
    asm volatile("ldmatrix.sync.aligned.m8n8.x4.trans.shared.b16 {%0,%1,%2,%3},[%4];"
                 : "=r"(r[0]), "=r"(r[1]), "=r"(r[2]), "=r"(r[3]) : "r"(saddr));
}

__device__ __forceinline__ uint32_t packh(__half a, __half b) {
    __half2 t; t.x = a; t.y = b;
    return *reinterpret_cast<uint32_t*>(&t);
}

__device__ __forceinline__ void cpa16(uint32_t dst, const void* src) {
    asm volatile("cp.async.cg.shared.global [%0], [%1], 16;" :: "r"(dst), "l"(src));
}
__device__ __forceinline__ void cpa_commit() { asm volatile("cp.async.commit_group;"); }
template<int N> __device__ __forceinline__ void cpa_wait() {
    asm volatile("cp.async.wait_group %0;" :: "n"(N));
}

// ============================================================================
// Prep: weights, all hi-only fp16.
// ============================================================================
__global__ void split_w_kernel(const float* __restrict__ Wq, const float* __restrict__ Wk,
                               const float* __restrict__ Wv, const float* __restrict__ Wo) {
    int np = 589824 / 2;
    for (int i = blockIdx.x * blockDim.x + threadIdx.x; i < np;
         i += gridDim.x * blockDim.x) {
        float2 v = ((const float2*)Wo)[i];
        ((uint32_t*)g_woh)[i] = packh(__float2half(v.x), __float2half(v.y));
        if (i < 24576) {
            float2 q = ((const float2*)Wq)[i];
            ((uint32_t*)g_wqh)[i] = packh(__float2half(q.x), __float2half(q.y));
            float2 k = ((const float2*)Wk)[i];
            ((uint32_t*)g_wkh)[i] = packh(__float2half(k.x), __float2half(k.y));
            float2 w = ((const float2*)Wv)[i];
            ((uint32_t*)g_wvh)[i] = packh(__float2half(w.x), __float2half(w.y));
        }
    }
}

// ============================================================================
// Kernel A: per-(window, head) fused QKV projection + attention, fp16.
// Planes: 0 x -> Sc(spans 0-1); 1 spare; 2 Wq -> V; 3 Wk; 4 Q -> P; 5 K; 6 Wv.
// ============================================================================
#define STBF  72
#define PLANE (64 * STBF)
#define PLB   (PLANE * 2)
#define SMEMB (7 * PLB)                // 64512 B
#define SCST  65

__device__ __forceinline__ void gemm_pass(float acc[2][4][4], uint32_t aBase,
                                          uint32_t bBase, int mbase, int nbase,
                                          int lane) {
    const int r16 = lane & 15;
    const uint32_t kaq = (lane >> 4) * 16;
    #pragma unroll
    for (int kc = 0; kc < 4; ++kc) {
        uint32_t ka = kaq + kc * 32;
        uint32_t a0[4], a1[4], b0[4], b1[4];
        ldsm4(a0, aBase + (mbase + r16) * 144 + ka);
        ldsm4(a1, aBase + (mbase + 16 + r16) * 144 + ka);
        ldsm4(b0, bBase + (nbase + r16) * 144 + ka);
        ldsm4(b1, bBase + (nbase + 16 + r16) * 144 + ka);
        mma_f16(acc[0][0], a0, b0[0], b0[2]);
        mma_f16(acc[0][1], a0, b0[1], b0[3]);
        mma_f16(acc[0][2], a0, b1[0], b1[2]);
        mma_f16(acc[0][3], a0, b1[1], b1[3]);
        mma_f16(acc[1][0], a1, b0[0], b0[2]);
        mma_f16(acc[1][1], a1, b0[1], b0[3]);
        mma_f16(acc[1][2], a1, b1[0], b1[2]);
        mma_f16(acc[1][3], a1, b1[1], b1[3]);
    }
}

// A row-major, B row-major [k][n] via ldmatrix.trans (for P @ V)
__device__ __forceinline__ void gemm_pass_tb(float acc[2][4][4], uint32_t aBase,
                                             uint32_t bBase, int mbase, int nbase,
                                             int lane) {
    const int r16 = lane & 15;
    const uint32_t kaq = (lane >> 4) * 16;
    const int krow = ((lane >> 4) << 3) + (lane & 7);
    const int nch = ((lane >> 3) & 1) * 8;
    #pragma unroll
    for (int kc = 0; kc < 4; ++kc) {
        uint32_t ka = kaq + kc * 32;
        uint32_t a0[4], a1[4], b0[4], b1[4];
        ldsm4(a0, aBase + (mbase + r16) * 144 + ka);
        ldsm4(a1, aBase + (mbase + 16 + r16) * 144 + ka);
        const uint32_t brow = bBase + (kc * 16 + krow) * 144;
        ldsm4t(b0, brow + (nbase + nch) * 2);
        ldsm4t(b1, brow + (nbase + 16 + nch) * 2);
        mma_f16(acc[0][0], a0, b0[0], b0[2]);
        mma_f16(acc[0][1], a0, b0[1], b0[3]);
        mma_f16(acc[0][2], a0, b1[0], b1[2]);
        mma_f16(acc[0][3], a0, b1[1], b1[3]);
        mma_f16(acc[1][0], a1, b0[0], b0[2]);
        mma_f16(acc[1][1], a1, b0[1], b0[3]);
        mma_f16(acc[1][2], a1, b1[0], b1[2]);
        mma_f16(acc[1][3], a1, b1[1], b1[3]);
    }
}

__global__ void __launch_bounds__(128, 3)
attn_kernel(const float* __restrict__ x)
{
    extern __shared__ __half sm[];
    __half* xh = sm;                 // -> Sc (spans planes 0-1)
    __half* pA = sm + 2 * PLANE;     // Wq -> V (row-major)
    __half* pB = sm + 3 * PLANE;     // Wk
    __half* pQ = sm + 4 * PLANE;     // Q -> P
    __half* pK = sm + 5 * PLANE;     // K
    float* Sc = (float*)sm;          // scores fp32 [64][65]

    const int tid = threadIdx.x, lane = tid & 31, wid = tid >> 5;
    const int warp_m = wid >> 1, warp_n = wid & 1;
    const int mbase = warp_m * 32, nbase = warp_n * 32;
    const int lr = lane >> 2, lc = lane & 3;

    const int h = blockIdx.x % NHEADS;
    const int n = blockIdx.x / NHEADS;
    const int b = n >> 6, hb = (n >> 3) & 7, wb = n & 7;

    const uint32_t sb = (uint32_t)__cvta_generic_to_shared(sm);
    const uint32_t sXH = sb;
    const uint32_t sPA = sb + 2 * PLB, sPB = sb + 3 * PLB;
    const uint32_t sPQ = sb + 4 * PLB, sPK = sb + 5 * PLB;
    const uint32_t sWV = sb + 6 * PLB;

    // ---- cp.async weights at entry (Wq->pA, Wk->pB, Wv->plane6) ----
    for (int q = tid; q < 1536; q += 128) {
        int pl = q >> 9;                   // 0..2
        int rem = q & 511, e = rem >> 3, ch = rem & 7;
        const __half* src = (pl == 0 ? g_wqh : pl == 1 ? g_wkh : g_wvh)
                            + h * 4096 + e * 64 + ch * 8;
        uint32_t dst = sb + (uint32_t)((pl < 2 ? (2 + pl) : 6) * PLB)
                       + e * 144 + ch * 16;
        cpa16(dst, src);
    }
    cpa_commit();

    // ---- stage x: fp32 loads -> fp16 single plane ----
    for (int q = tid; q < 512; q += 128) {
        int l = q >> 3, ch = q & 7;
        uint4 hv = make_uint4(0, 0, 0, 0);
        if (l < LW) {
            int i = l / 7, j = l - i * 7;
            const float* src = x + (((size_t)(b * 56 + hb * 7 + i)) * 56 + (wb * 7 + j)) * CCH
                               + h * DH + ch * 8;
            float4 f0 = *(const float4*)src;
            float4 f1 = *(const float4*)(src + 4);
            hv.x = packh(__float2half(f0.x), __float2half(f0.y));
            hv.y = packh(__float2half(f0.z), __float2half(f0.w));
            hv.z = packh(__float2half(f1.x), __float2half(f1.y));
            hv.w = packh(__float2half(f1.z), __float2half(f1.w));
        }
        *(uint4*)(xh + l * STBF + ch * 8) = hv;
    }
    cpa_wait<0>();
    __syncthreads();

    // ---- merged Q & K projections (shared A frags) ----
    {
        float aq[2][4][4] = {}, ak[2][4][4] = {};
        const int r16 = lane & 15;
        const uint32_t kaq = (lane >> 4) * 16;
        #pragma unroll
        for (int kc = 0; kc < 4; ++kc) {
            uint32_t ka = kaq + kc * 32;
            uint32_t a0[4], a1[4], bq0[4], bq1[4], bk0[4], bk1[4];
            ldsm4(a0, sXH + (mbase + r16) * 144 + ka);
            ldsm4(a1, sXH + (mbase + 16 + r16) * 144 + ka);
            ldsm4(bq0, sPA + (nbase + r16) * 144 + ka);
            ldsm4(bq1, sPA + (nbase + 16 + r16) * 144 + ka);
            ldsm4(bk0, sPB + (nbase + r16) * 144 + ka);
            ldsm4(bk1, sPB + (nbase + 16 + r16) * 144 + ka);
            mma_f16(aq[0][0], a0, bq0[0], bq0[2]);
            mma_f16(aq[0][1], a0, bq0[1], bq0[3]);
            mma_f16(aq[0][2], a0, bq1[0], bq1[2]);
            mma_f16(aq[0][3], a0, bq1[1], bq1[3]);
            mma_f16(aq[1][0], a1, bq0[0], bq0[2]);
            mma_f16(aq[1][1], a1, bq0[1], bq0[3]);
            mma_f16(aq[1][2], a1, bq1[0], bq1[2]);
            mma_f16(aq[1][3], a1, bq1[1], bq1[3]);
            mma_f16(ak[0][0], a0, bk0[0], bk0[2]);
            mma_f16(ak[0][1], a0, bk0[1], bk0[3]);
            mma_f16(ak[0][2], a0, bk1[0], bk1[2]);
            mma_f16(ak[0][3], a0, bk1[1], bk1[3]);
            mma_f16(ak[1][0], a1, bk0[0], bk0[2]);
            mma_f16(ak[1][1], a1, bk0[1], bk0[3]);
            mma_f16(ak[1][2], a1, bk1[0], bk1[2]);
            mma_f16(ak[1][3], a1, bk1[1], bk1[3]);
        }
        uint32_t* OQ = (uint32_t*)pQ;
        uint32_t* OK = (uint32_t*)pK;
        #pragma unroll
        for (int f = 0; f < 2; ++f)
            #pragma unroll
            for (int g = 0; g < 4; ++g) {
                int r = mbase + 16 * f + lr;
                int w = r * 36 + (nbase + 8 * g) / 2 + lc;
                OQ[w] = packh(__float2half(aq[f][g][0]), __float2half(aq[f][g][1]));
                OQ[w + 8 * 36] = packh(__float2half(aq[f][g][2]), __float2half(aq[f][g][3]));
                OK[w] = packh(__float2half(ak[f][g][0]), __float2half(ak[f][g][1]));
                OK[w + 8 * 36] = packh(__float2half(ak[f][g][2]), __float2half(ak[f][g][3]));
            }
    }
    __syncthreads();                        // pA/pB free after this

    // ---- V = x @ Wv (1 pass), store row-major in pA ----
    {
        float acc[2][4][4] = {};
        gemm_pass(acc, sXH, sWV, mbase, nbase, lane);
        uint32_t* OV = (uint32_t*)pA;
        #pragma unroll
        for (int f = 0; f < 2; ++f)
            #pragma unroll
            for (int g = 0; g < 4; ++g) {
                int r = mbase + 16 * f + lr;
                int w = r * 36 + (nbase + 8 * g) / 2 + lc;
                OV[w] = packh(__float2half(acc[f][g][0]), __float2half(acc[f][g][1]));
                OV[w + 8 * 36] = packh(__float2half(acc[f][g][2]), __float2half(acc[f][g][3]));
            }
    }
    __syncthreads();                        // xh free after this

    // ---- scores = Q @ K^T, scale + mask -> Sc ----
    {
        float acc[2][4][4] = {};
        gemm_pass(acc, sPQ, sPK, mbase, nbase, lane);
        #pragma unroll
        for (int f = 0; f < 2; ++f)
            #pragma unroll
            for (int g = 0; g < 4; ++g) {
                int r = mbase + 16 * f + lr;
                int c = nbase + 8 * g + 2 * lc;
                Sc[r * SCST + c]           = (c     < LW) ? acc[f][g][0] * 0.125f : -1e30f;
                Sc[r * SCST + c + 1]       = (c + 1 < LW) ? acc[f][g][1] * 0.125f : -1e30f;
                Sc[(r + 8) * SCST + c]     = (c     < LW) ? acc[f][g][2] * 0.125f : -1e30f;
                Sc[(r + 8) * SCST + c + 1] = (c + 1 < LW) ? acc[f][g][3] * 0.125f : -1e30f;
            }
    }
    __syncthreads();                        // pQ/pK free after this

    // ---- softmax: 2 threads per row, write P (hi only) into pQ ----
    if (tid < 2 * LW) {
        const int r = tid >> 1, half = tid & 1;
        const unsigned msk = (tid < 96) ? 0xFFFFFFFFu : 0x3u;
        float* row = Sc + r * SCST;
        const int m0 = half ? 25 : 0, m1 = half ? LW : 25;
        float mx = -1e30f;
        #pragma unroll
        for (int m = m0; m < m1; ++m) mx = fmaxf(mx, row[m]);
        mx = fmaxf(mx, __shfl_xor_sync(msk, mx, 1));
        float s = 0.f;
        #pragma unroll
        for (int m = m0; m < m1; ++m) { float e = __expf(row[m] - mx); row[m] = e; s += e; }
        s += __shfl_xor_sync(msk, s, 1);
        float inv = 1.f / s;
        __syncwarp(msk);
        uint32_t* ph = (uint32_t*)(pQ + r * STBF);
        #pragma unroll
        for (int mw = half * 16; mw < half * 16 + 16; ++mw) {
            int mc = 2 * mw;
            float p0 = (mc     < LW) ? row[mc] * inv     : 0.f;
            float p1 = (mc + 1 < LW) ? row[mc + 1] * inv : 0.f;
            ph[mw] = packh(__float2half(p0), __float2half(p1));
        }
    }
    __syncthreads();

    // ---- out = P @ V (1 pass, trans-B ldsm), store fp16 to g_sh ----
    {
        float acc[2][4][4] = {};
        gemm_pass_tb(acc, sPQ, sPA, mbase, nbase, lane);
        #pragma unroll
        for (int f = 0; f < 2; ++f)
            #pragma unroll
            for (int g = 0; g < 4; ++g) {
                int r = mbase + 16 * f + lr;
                int c = nbase + 8 * g + 2 * lc;
                if (r < LW) {
                    size_t off = ((size_t)n * LW + r) * CCH + h * DH + c;
                    *(uint32_t*)(g_sh + off) =
                        packh(__float2half(acc[f][g][0]), __float2half(acc[f][g][1]));
                }
                if (r + 8 < LW) {
                    size_t off = ((size_t)n * LW + r + 8) * CCH + h * DH + c;
                    *(uint32_t*)(g_sh + off) =
                        packh(__float2half(acc[f][g][2]), __float2half(acc[f][g][3]));
                }
            }
    }
}

// ============================================================================
// Kernel B: y = S @ Wo^T + bo, pure fp16 GEMM (1-term).
// 3-stage cp.async pipeline, swizzled 64B rows, 128x64 block, BK=32.
// ============================================================================
#define PSTG 12288                     // bytes per stage (A 8192, B 4096)
#define QA   0
#define QB   8192
#define PROJ_SMEM (3 * PSTG)           // 36864 B

__device__ __forceinline__ uint32_t swr(int row, int ch) {
    return (uint32_t)(row * 64 + ((ch ^ ((row >> 1) & 3)) << 4));
}

__device__ __forceinline__ void proj_stage(uint32_t sb, int s, int kt,
                                           int m_base, int n_base, int tid) {
    const uint32_t base = sb + s * PSTG;
    #pragma unroll
    for (int c = tid; c < 512; c += 256) {         // A: 128 rows x 4 chunks
        int row = c >> 2, ch = c & 3;
        cpa16(base + QA + swr(row, ch),
              g_sh + (size_t)(m_base + row) * CCH + kt + ch * 8);
    }
    {                                              // B: 64 rows x 4 chunks
        int row = tid >> 2, ch = tid & 3;
        if (tid < 256)
            cpa16(base + QB + swr(row, ch),
                  g_woh + (size_t)(n_base + row) * CCH + kt + ch * 8);
    }
    cpa_commit();
}

__global__ void __launch_bounds__(256, 3)
proj_kernel(const float* __restrict__ bo, float* __restrict__ y)
{
    extern __shared__ __half psm[];
    const int tid = threadIdx.x, lane = tid & 31, wid = tid >> 5;
    const int warp_m = wid >> 1, warp_n = wid & 1;
    const int lr = lane >> 2, lc = lane & 3;
    const int n_base = (blockIdx.x % 12) * 64;
    const int m_base = (blockIdx.x / 12) * 128;
    const uint32_t sb = (uint32_t)__cvta_generic_to_shared(psm);
    const int r16 = lane & 15;
    const int colq = (lane >> 4);

    float acc[2][4][4] = {};

    auto compute = [&](int s) {
        const uint32_t base = sb + s * PSTG;
        const uint32_t aB = base + QA;
        const uint32_t bB = base + QB;
        #pragma unroll
        for (int kc = 0; kc < 2; ++kc) {
            const int ch = colq + kc * 2;
            const int ra0 = warp_m * 32 + r16, ra1 = ra0 + 16;
            const int rb0 = warp_n * 32 + r16, rb1 = rb0 + 16;
            uint32_t a0[4], a1[4], b0[4], b1[4];
            ldsm4(a0, aB + swr(ra0, ch));
            ldsm4(a1, aB + swr(ra1, ch));
            ldsm4(b0, bB + swr(rb0, ch));
            ldsm4(b1, bB + swr(rb1, ch));
            mma_f16(acc[0][0], a0, b0[0], b0[2]);
            mma_f16(acc[0][1], a0, b0[1], b0[3]);
            mma_f16(acc[0][2], a0, b1[0], b1[2]);
            mma_f16(acc[0][3], a0, b1[1], b1[3]);
            mma_f16(acc[1][0], a1, b0[0], b0[2]);
            mma_f16(acc[1][1], a1, b0[1], b0[3]);
            mma_f16(acc[1][2], a1, b1[0], b1[2]);
            mma_f16(acc[1][3], a1, b1[1], b1[3]);
        }
    };

    proj_stage(sb, 0, 0, m_base, n_base, tid);
    proj_stage(sb, 1, 32, m_base, n_base, tid);
    #pragma unroll 1
    for (int t = 0; t < 24; ++t) {
        if (t < 23) cpa_wait<1>(); else cpa_wait<0>();
        __syncthreads();
        compute(t % 3);
        if (t + 2 < 24) proj_stage(sb, (t + 2) % 3, (t + 2) * 32, m_base, n_base, tid);
    }

    #pragma unroll
    for (int g = 0; g < 4; ++g) {
        int c = n_base + warp_n * 32 + 8 * g + 2 * lc;
        float b0 = bo[c], b1 = bo[c + 1];
        #pragma unroll
        for (int f = 0; f < 2; ++f) {
            int r = m_base + warp_m * 32 + 16 * f + lr;
            *(float2*)&y[(size_t)r * CCH + c] =
                make_float2(acc[f][g][0] + b0, acc[f][g][1] + b1);
            *(float2*)&y[(size_t)(r + 8) * CCH + c] =
                make_float2(acc[f][g][2] + b0, acc[f][g][3] + b1);
        }
    }
}

// ============================================================================
extern "C" void kernel_launch(void* const* d_in, const int* in_sizes, int n_in,
                              void* d_out, int out_size)
{
    const float* x  = (const float*)d_in[0];
    const float* Wq = (const float*)d_in[1];
    const float* Wk = (const float*)d_in[2];
    const float* Wv = (const float*)d_in[3];
    const float* Wo = (const float*)d_in[4];
    const float* bo = (const float*)d_in[5];
    float* y = (float*)d_out;

    cudaFuncSetAttribute(attn_kernel, cudaFuncAttributeMaxDynamicSharedMemorySize, SMEMB);
    cudaFuncSetAttribute(proj_kernel, cudaFuncAttributeMaxDynamicSharedMemorySize, PROJ_SMEM);

    split_w_kernel<<<576, 256>>>(Wq, Wk, Wv, Wo);
    attn_kernel<<<NWIN * NHEADS, 128, SMEMB>>>(x);
    proj_kernel<<<784 * 12, 256, PROJ_SMEM>>>(bo, y);
}

// round 11
// speedup vs baseline: 2.0209x; 1.1055x over previous
#include <cuda_runtime.h>
#include <cuda_fp16.h>
#include <stdint.h>
#include <math.h>

#define NHEADS 12
#define DH     64
#define LW     49
#define CCH    768
#define NWIN   2048
#define MROWS  (NWIN * LW)                 // 100352

// ---------------- device-global fp16 planes --------------------------------
__device__ __half g_sh[(size_t)MROWS * CCH];          // attention out
__device__ __half g_wqh[12 * 4096], g_wkh[12 * 4096], g_wvh[12 * 4096];
__device__ __half g_woh[589824];

// ---------------- helpers ---------------------------------------------------
__device__ __forceinline__ void mma_f16(float c[4], const uint32_t a[4],
                                        uint32_t b0, uint32_t b1) {
    asm volatile(
        "mma.sync.aligned.m16n8k16.row.col.f32.f16.f16.f32 "
        "{%0,%1,%2,%3},{%4,%5,%6,%7},{%8,%9},{%0,%1,%2,%3};\n"
        : "+f"(c[0]), "+f"(c[1]), "+f"(c[2]), "+f"(c[3])
        : "r"(a[0]), "r"(a[1]), "r"(a[2]), "r"(a[3]), "r"(b0), "r"(b1));
}

__device__ __forceinline__ void ldsm4(uint32_t r[4], uint32_t saddr) {
    asm volatile("ldmatrix.sync.aligned.m8n8.x4.shared.b16 {%0,%1,%2,%3},[%4];"
                 : "=r"(r[0]), "=r"(r[1]), "=r"(r[2]), "=r"(r[3]) : "r"(saddr));
}

__device__ __forceinline__ void ldsm4t(uint32_t r[4], uint32_t saddr) {
    asm volatile("ldmatrix.sync.aligned.m8n8.x4.trans.shared.b16 {%0,%1,%2,%3},[%4];"
                 : "=r"(r[0]), "=r"(r[1]), "=r"(r[2]), "=r"(r[3]) : "r"(saddr));
}

__device__ __forceinline__ uint32_t packh(__half a, __half b) {
    __half2 t; t.x = a; t.y = b;
    return *reinterpret_cast<uint32_t*>(&t);
}

__device__ __forceinline__ void cpa16(uint32_t dst, const void* src) {
    asm volatile("cp.async.cg.shared.global [%0], [%1], 16;" :: "r"(dst), "l"(src));
}
__device__ __forceinline__ void cpa_commit() { asm volatile("cp.async.commit_group;"); }
template<int N> __device__ __forceinline__ void cpa_wait() {
    asm volatile("cp.async.wait_group %0;" :: "n"(N));
}

// SW128-swizzled byte offset within a plane of 128-B rows.
// row&7 XORed into the 16-B chunk index (bits [4:7)). Low 4 bits untouched.
__device__ __forceinline__ uint32_t swo(int row, uint32_t col) {
    return ((uint32_t)row << 7) + (col ^ (((uint32_t)row & 7u) << 4));
}

// ============================================================================
// Prep: weights, all hi-only fp16.
// ============================================================================
__global__ void split_w_kernel(const float* __restrict__ Wq, const float* __restrict__ Wk,
                               const float* __restrict__ Wv, const float* __restrict__ Wo) {
    int np = 589824 / 2;
    for (int i = blockIdx.x * blockDim.x + threadIdx.x; i < np;
         i += gridDim.x * blockDim.x) {
        float2 v = ((const float2*)Wo)[i];
        ((uint32_t*)g_woh)[i] = packh(__float2half(v.x), __float2half(v.y));
        if (i < 24576) {
            float2 q = ((const float2*)Wq)[i];
            ((uint32_t*)g_wqh)[i] = packh(__float2half(q.x), __float2half(q.y));
            float2 k = ((const float2*)Wk)[i];
            ((uint32_t*)g_wkh)[i] = packh(__float2half(k.x), __float2half(k.y));
            float2 w = ((const float2*)Wv)[i];
            ((uint32_t*)g_wvh)[i] = packh(__float2half(w.x), __float2half(w.y));
        }
    }
}

// ============================================================================
// Kernel A: fused QKV projection + attention, fp16, SW128 unpadded planes.
// Planes (8192 B each): 0=x  1=Wq  2=Wk->V  3=Q->P  4=K  5=Wv
// Sc (fp32 [49][65], 12740 B) aliases planes 0-1 after x/Wq die.
// ============================================================================
#define PLB   8192
#define SMEMB (6 * PLB)                // 49152 B -> 4 CTAs/SM
#define SCST  65

__device__ __forceinline__ void gemm_pass(float acc[2][4][4], uint32_t aBase,
                                          uint32_t bBase, int mbase, int nbase,
                                          int lane) {
    const int r16 = lane & 15;
    const uint32_t kaq = (lane >> 4) * 16;
    #pragma unroll
    for (int kc = 0; kc < 4; ++kc) {
        uint32_t ka = kaq + kc * 32;
        uint32_t a0[4], a1[4], b0[4], b1[4];
        uint32_t a0a = aBase + swo(mbase + r16, ka);
        uint32_t b0a = bBase + swo(nbase + r16, ka);
        ldsm4(a0, a0a);
        ldsm4(a1, a0a + 2048);             // row+16: same swizzle phase
        ldsm4(b0, b0a);
        ldsm4(b1, b0a + 2048);
        mma_f16(acc[0][0], a0, b0[0], b0[2]);
        mma_f16(acc[0][1], a0, b0[1], b0[3]);
        mma_f16(acc[0][2], a0, b1[0], b1[2]);
        mma_f16(acc[0][3], a0, b1[1], b1[3]);
        mma_f16(acc[1][0], a1, b0[0], b0[2]);
        mma_f16(acc[1][1], a1, b0[1], b0[3]);
        mma_f16(acc[1][2], a1, b1[0], b1[2]);
        mma_f16(acc[1][3], a1, b1[1], b1[3]);
    }
}

// A row-major, B row-major [k][n] via ldmatrix.trans (for P @ V)
__device__ __forceinline__ void gemm_pass_tb(float acc[2][4][4], uint32_t aBase,
                                             uint32_t bBase, int mbase, int nbase,
                                             int lane) {
    const int r16 = lane & 15;
    const uint32_t kaq = (lane >> 4) * 16;
    const int krow = ((lane >> 4) << 3) + (lane & 7);
    const int nch = ((lane >> 3) & 1) * 8;
    #pragma unroll
    for (int kc = 0; kc < 4; ++kc) {
        uint32_t ka = kaq + kc * 32;
        uint32_t a0[4], a1[4], b0[4], b1[4];
        uint32_t a0a = aBase + swo(mbase + r16, ka);
        ldsm4(a0, a0a);
        ldsm4(a1, a0a + 2048);
        const int rowB = kc * 16 + krow;
        ldsm4t(b0, bBase + swo(rowB, (nbase + nch) * 2));
        ldsm4t(b1, bBase + swo(rowB, (nbase + 16 + nch) * 2));
        mma_f16(acc[0][0], a0, b0[0], b0[2]);
        mma_f16(acc[0][1], a0, b0[1], b0[3]);
        mma_f16(acc[0][2], a0, b1[0], b1[2]);
        mma_f16(acc[0][3], a0, b1[1], b1[3]);
        mma_f16(acc[1][0], a1, b0[0], b0[2]);
        mma_f16(acc[1][1], a1, b0[1], b0[3]);
        mma_f16(acc[1][2], a1, b1[0], b1[2]);
        mma_f16(acc[1][3], a1, b1[1], b1[3]);
    }
}

__global__ void __launch_bounds__(128, 4)
attn_kernel(const float* __restrict__ x)
{
    extern __shared__ char smc[];
    float* Sc = (float*)smc;               // fp32 scores, aliases planes 0-1

    const int tid = threadIdx.x, lane = tid & 31, wid = tid >> 5;
    const int warp_m = wid >> 1, warp_n = wid & 1;
    const int mbase = warp_m * 32, nbase = warp_n * 32;
    const int lr = lane >> 2, lc = lane & 3;

    const int h = blockIdx.x % NHEADS;
    const int n = blockIdx.x / NHEADS;
    const int b = n >> 6, hb = (n >> 3) & 7, wb = n & 7;

    const uint32_t sb = (uint32_t)__cvta_generic_to_shared(smc);
    const uint32_t sX = sb, sWQ = sb + PLB, sWK = sb + 2 * PLB;
    const uint32_t sV = sb + 2 * PLB;      // V overwrites Wk
    const uint32_t sQ = sb + 3 * PLB;      // Q, later P
    const uint32_t sK = sb + 4 * PLB;
    const uint32_t sWV = sb + 5 * PLB;

    // ---- cp.async weights at entry (Wq->1, Wk->2, Wv->5), swizzled ----
    for (int q = tid; q < 1536; q += 128) {
        int pl = q >> 9;                   // 0..2
        int rem = q & 511, e = rem >> 3, ch = rem & 7;
        const __half* src = (pl == 0 ? g_wqh : pl == 1 ? g_wkh : g_wvh)
                            + h * 4096 + e * 64 + ch * 8;
        uint32_t plane = (pl == 0) ? 1u : (pl == 1) ? 2u : 5u;
        cpa16(sb + plane * PLB + swo(e, ch * 16), src);
    }
    cpa_commit();

    // ---- stage x: fp32 loads -> fp16, swizzled 16-B stores; pad rows 0 ----
    for (int q = tid; q < 512; q += 128) {
        int l = q >> 3, ch = q & 7;
        uint4 hv = make_uint4(0, 0, 0, 0);
        if (l < LW) {
            int i = l / 7, j = l - i * 7;
            const float* src = x + (((size_t)(b * 56 + hb * 7 + i)) * 56 + (wb * 7 + j)) * CCH
                               + h * DH + ch * 8;
            float4 f0 = *(const float4*)src;
            float4 f1 = *(const float4*)(src + 4);
            hv.x = packh(__float2half(f0.x), __float2half(f0.y));
            hv.y = packh(__float2half(f0.z), __float2half(f0.w));
            hv.z = packh(__float2half(f1.x), __float2half(f1.y));
            hv.w = packh(__float2half(f1.z), __float2half(f1.w));
        }
        *(uint4*)(smc + swo(l, ch * 16)) = hv;
    }
    cpa_wait<0>();
    __syncthreads();                        // barrier 1

    // ---- merged Q & K projections (shared A frags) ----
    {
        float aq[2][4][4] = {}, ak[2][4][4] = {};
        const int r16 = lane & 15;
        const uint32_t kaq = (lane >> 4) * 16;
        #pragma unroll
        for (int kc = 0; kc < 4; ++kc) {
            uint32_t ka = kaq + kc * 32;
            uint32_t a0[4], a1[4], bq0[4], bq1[4], bk0[4], bk1[4];
            uint32_t a0a = sX + swo(mbase + r16, ka);
            uint32_t q0a = sWQ + swo(nbase + r16, ka);
            uint32_t k0a = sWK + swo(nbase + r16, ka);
            ldsm4(a0, a0a);  ldsm4(a1, a0a + 2048);
            ldsm4(bq0, q0a); ldsm4(bq1, q0a + 2048);
            ldsm4(bk0, k0a); ldsm4(bk1, k0a + 2048);
            mma_f16(aq[0][0], a0, bq0[0], bq0[2]);
            mma_f16(aq[0][1], a0, bq0[1], bq0[3]);
            mma_f16(aq[0][2], a0, bq1[0], bq1[2]);
            mma_f16(aq[0][3], a0, bq1[1], bq1[3]);
            mma_f16(aq[1][0], a1, bq0[0], bq0[2]);
            mma_f16(aq[1][1], a1, bq0[1], bq0[3]);
            mma_f16(aq[1][2], a1, bq1[0], bq1[2]);
            mma_f16(aq[1][3], a1, bq1[1], bq1[3]);
            mma_f16(ak[0][0], a0, bk0[0], bk0[2]);
            mma_f16(ak[0][1], a0, bk0[1], bk0[3]);
            mma_f16(ak[0][2], a0, bk1[0], bk1[2]);
            mma_f16(ak[0][3], a0, bk1[1], bk1[3]);
            mma_f16(ak[1][0], a1, bk0[0], bk0[2]);
            mma_f16(ak[1][1], a1, bk0[1], bk0[3]);
            mma_f16(ak[1][2], a1, bk1[0], bk1[2]);
            mma_f16(ak[1][3], a1, bk1[1], bk1[3]);
        }
        #pragma unroll
        for (int f = 0; f < 2; ++f)
            #pragma unroll
            for (int g = 0; g < 4; ++g) {
                int r = mbase + 16 * f + lr;
                uint32_t off = swo(r, (uint32_t)(nbase + 8 * g + 2 * lc) * 2);
                *(uint32_t*)(smc + 3 * PLB + off) =
                    packh(__float2half(aq[f][g][0]), __float2half(aq[f][g][1]));
                *(uint32_t*)(smc + 3 * PLB + off + 1024) =
                    packh(__float2half(aq[f][g][2]), __float2half(aq[f][g][3]));
                *(uint32_t*)(smc + 4 * PLB + off) =
                    packh(__float2half(ak[f][g][0]), __float2half(ak[f][g][1]));
                *(uint32_t*)(smc + 4 * PLB + off + 1024) =
                    packh(__float2half(ak[f][g][2]), __float2half(ak[f][g][3]));
            }
    }
    __syncthreads();                        // barrier 2 (Wq/Wk dead)

    // ---- V = x @ Wv (1 pass), store row-major into plane 2 ----
    {
        float acc[2][4][4] = {};
        gemm_pass(acc, sX, sWV, mbase, nbase, lane);
        #pragma unroll
        for (int f = 0; f < 2; ++f)
            #pragma unroll
            for (int g = 0; g < 4; ++g) {
                int r = mbase + 16 * f + lr;
                uint32_t off = swo(r, (uint32_t)(nbase + 8 * g + 2 * lc) * 2);
                *(uint32_t*)(smc + 2 * PLB + off) =
                    packh(__float2half(acc[f][g][0]), __float2half(acc[f][g][1]));
                *(uint32_t*)(smc + 2 * PLB + off + 1024) =
                    packh(__float2half(acc[f][g][2]), __float2half(acc[f][g][3]));
            }
    }
    __syncthreads();                        // barrier 3 (x dead)

    // ---- scores = Q @ K^T, scale -> Sc (rows < 49 only) ----
    {
        float acc[2][4][4] = {};
        gemm_pass(acc, sQ, sK, mbase, nbase, lane);
        #pragma unroll
        for (int f = 0; f < 2; ++f)
            #pragma unroll
            for (int g = 0; g < 4; ++g) {
                int r = mbase + 16 * f + lr;
                int c = nbase + 8 * g + 2 * lc;
                if (r < LW) {
                    Sc[r * SCST + c]     = acc[f][g][0] * 0.125f;
                    Sc[r * SCST + c + 1] = acc[f][g][1] * 0.125f;
                }
                if (r + 8 < LW) {
                    Sc[(r + 8) * SCST + c]     = acc[f][g][2] * 0.125f;
                    Sc[(r + 8) * SCST + c + 1] = acc[f][g][3] * 0.125f;
                }
            }
    }
    __syncthreads();                        // barrier 4 (Q consumed)

    // ---- softmax: 2 threads per row, write P into plane 3 (over Q) ----
    if (tid < 2 * LW) {
        const int r = tid >> 1, half = tid & 1;
        const unsigned msk = (tid < 96) ? 0xFFFFFFFFu : 0x3u;
        float* row = Sc + r * SCST;
        const int m0 = half ? 25 : 0, m1 = half ? LW : 25;
        float mx = -1e30f;
        #pragma unroll
        for (int m = m0; m < m1; ++m) mx = fmaxf(mx, row[m]);
        mx = fmaxf(mx, __shfl_xor_sync(msk, mx, 1));
        float s = 0.f;
        #pragma unroll
        for (int m = m0; m < m1; ++m) { float e = __expf(row[m] - mx); row[m] = e; s += e; }
        s += __shfl_xor_sync(msk, s, 1);
        float inv = 1.f / s;
        __syncwarp(msk);
        #pragma unroll
        for (int mw = half * 16; mw < half * 16 + 16; ++mw) {
            int mc = 2 * mw;
            float p0 = (mc     < LW) ? row[mc] * inv     : 0.f;
            float p1 = (mc + 1 < LW) ? row[mc + 1] * inv : 0.f;
            *(uint32_t*)(smc + 3 * PLB + swo(r, (uint32_t)mw * 4)) =
                packh(__float2half(p0), __float2half(p1));
        }
    }
    __syncthreads();                        // barrier 5

    // ---- out = P @ V (trans-B ldsm), store fp16 to g_sh ----
    // (P rows >= 49 are stale Q data; output rows >= 49 predicated away.)
    {
        float acc[2][4][4] = {};
        gemm_pass_tb(acc, sQ, sV, mbase, nbase, lane);
        #pragma unroll
        for (int f = 0; f < 2; ++f)
            #pragma unroll
            for (int g = 0; g < 4; ++g) {
                int r = mbase + 16 * f + lr;
                int c = nbase + 8 * g + 2 * lc;
                if (r < LW) {
                    size_t off = ((size_t)n * LW + r) * CCH + h * DH + c;
                    *(uint32_t*)(g_sh + off) =
                        packh(__float2half(acc[f][g][0]), __float2half(acc[f][g][1]));
                }
                if (r + 8 < LW) {
                    size_t off = ((size_t)n * LW + r + 8) * CCH + h * DH + c;
                    *(uint32_t*)(g_sh + off) =
                        packh(__float2half(acc[f][g][2]), __float2half(acc[f][g][3]));
                }
            }
    }
}

// ============================================================================
// Kernel B: y = S @ Wo^T + bo, pure fp16 GEMM, BK=64, SW128 128-B rows,
// 3-stage cp.async pipeline, 128x64 block, 256 threads.
// ============================================================================
#define PSTG 24576                     // A 16384 + B 8192
#define QA   0
#define QB   16384
#define PROJ_SMEM (3 * PSTG)           // 73728 B -> 3 CTAs/SM

__device__ __forceinline__ void proj_stage(uint32_t sb, int s, int kt,
                                           int m_base, int n_base, int tid) {
    const uint32_t base = sb + s * PSTG;
    #pragma unroll
    for (int c = tid; c < 1024; c += 256) {        // A: 128 rows x 8 chunks
        int row = c >> 3, ch = c & 7;
        cpa16(base + QA + swo(row, ch * 16),
              g_sh + (size_t)(m_base + row) * CCH + kt + ch * 8);
    }
    #pragma unroll
    for (int c = tid; c < 512; c += 256) {         // B: 64 rows x 8 chunks
        int row = c >> 3, ch = c & 7;
        cpa16(base + QB + swo(row, ch * 16),
              g_woh + (size_t)(n_base + row) * CCH + kt + ch * 8);
    }
    cpa_commit();
}

__global__ void __launch_bounds__(256, 3)
proj_kernel(const float* __restrict__ bo, float* __restrict__ y)
{
    extern __shared__ char psm[];
    const int tid = threadIdx.x, lane = tid & 31, wid = tid >> 5;
    const int warp_m = wid >> 1, warp_n = wid & 1;
    const int lr = lane >> 2, lc = lane & 3;
    const int n_base = (blockIdx.x % 12) * 64;
    const int m_base = (blockIdx.x / 12) * 128;
    const uint32_t sb = (uint32_t)__cvta_generic_to_shared(psm);
    const int r16 = lane & 15;
    const uint32_t kaq = (lane >> 4) * 16;

    float acc[2][4][4] = {};

    auto compute = [&](int s) {
        const uint32_t aB = sb + s * PSTG + QA;
        const uint32_t bB = sb + s * PSTG + QB;
        #pragma unroll
        for (int kc = 0; kc < 4; ++kc) {
            uint32_t ka = kaq + kc * 32;
            uint32_t a0[4], a1[4], b0[4], b1[4];
            uint32_t a0a = aB + swo(warp_m * 32 + r16, ka);
            uint32_t b0a = bB + swo(warp_n * 32 + r16, ka);
            ldsm4(a0, a0a);
            ldsm4(a1, a0a + 2048);
            ldsm4(b0, b0a);
            ldsm4(b1, b0a + 2048);
            mma_f16(acc[0][0], a0, b0[0], b0[2]);
            mma_f16(acc[0][1], a0, b0[1], b0[3]);
            mma_f16(acc[0][2], a0, b1[0], b1[2]);
            mma_f16(acc[0][3], a0, b1[1], b1[3]);
            mma_f16(acc[1][0], a1, b0[0], b0[2]);
            mma_f16(acc[1][1], a1, b0[1], b0[3]);
            mma_f16(acc[1][2], a1, b1[0], b1[2]);
            mma_f16(acc[1][3], a1, b1[1], b1[3]);
        }
    };

    proj_stage(sb, 0, 0, m_base, n_base, tid);
    proj_stage(sb, 1, 64, m_base, n_base, tid);
    #pragma unroll 1
    for (int t = 0; t < 12; ++t) {
        if (t < 11) cpa_wait<1>(); else cpa_wait<0>();
        __syncthreads();
        compute(t % 3);
        if (t + 2 < 12) proj_stage(sb, (t + 2) % 3, (t + 2) * 64, m_base, n_base, tid);
    }

    #pragma unroll
    for (int g = 0; g < 4; ++g) {
        int c = n_base + warp_n * 32 + 8 * g + 2 * lc;
        float b0 = bo[c], b1 = bo[c + 1];
        #pragma unroll
        for (int f = 0; f < 2; ++f) {
            int r = m_base + warp_m * 32 + 16 * f + lr;
            *(float2*)&y[(size_t)r * CCH + c] =
                make_float2(acc[f][g][0] + b0, acc[f][g][1] + b1);
            *(float2*)&y[(size_t)(r + 8) * CCH + c] =
                make_float2(acc[f][g][2] + b0, acc[f][g][3] + b1);
        }
    }
}

// ============================================================================
extern "C" void kernel_launch(void* const* d_in, const int* in_sizes, int n_in,
                              void* d_out, int out_size)
{
    const float* x  = (const float*)d_in[0];
    const float* Wq = (const float*)d_in[1];
    const float* Wk = (const float*)d_in[2];
    const float* Wv = (const float*)d_in[3];
    const float* Wo = (const float*)d_in[4];
    const float* bo = (const float*)d_in[5];
    float* y = (float*)d_out;

    cudaFuncSetAttribute(attn_kernel, cudaFuncAttributeMaxDynamicSharedMemorySize, SMEMB);
    cudaFuncSetAttribute(proj_kernel, cudaFuncAttributeMaxDynamicSharedMemorySize, PROJ_SMEM);

    split_w_kernel<<<576, 256>>>(Wq, Wk, Wv, Wo);
    attn_kernel<<<NWIN * NHEADS, 128, SMEMB>>>(x);
    proj_kernel<<<784 * 12, 256, PROJ_SMEM>>>(bo, y);
}

// round 12
// speedup vs baseline: 2.1530x; 1.0654x over previous
#include <cuda_runtime.h>
#include <cuda_fp16.h>
#include <stdint.h>
#include <math.h>

#define NHEADS 12
#define DH     64
#define LW     49
#define CCH    768
#define NWIN   2048
#define MROWS  (NWIN * LW)                 // 100352

// ---------------- device-global fp16 planes --------------------------------
__device__ __half g_sh[(size_t)MROWS * CCH];          // attention out
__device__ __half g_wqh[12 * 4096], g_wkh[12 * 4096], g_wvh[12 * 4096];
__device__ __half g_woh[589824];

// ---------------- helpers ---------------------------------------------------
__device__ __forceinline__ void mma_f16(float c[4], const uint32_t a[4],
                                        uint32_t b0, uint32_t b1) {
    asm volatile(
        "mma.sync.aligned.m16n8k16.row.col.f32.f16.f16.f32 "
        "{%0,%1,%2,%3},{%4,%5,%6,%7},{%8,%9},{%0,%1,%2,%3};\n"
        : "+f"(c[0]), "+f"(c[1]), "+f"(c[2]), "+f"(c[3])
        : "r"(a[0]), "r"(a[1]), "r"(a[2]), "r"(a[3]), "r"(b0), "r"(b1));
}

__device__ __forceinline__ void ldsm4(uint32_t r[4], uint32_t saddr) {
    asm volatile("ldmatrix.sync.aligned.m8n8.x4.shared.b16 {%0,%1,%2,%3},[%4];"
                 : "=r"(r[0]), "=r"(r[1]), "=r"(r[2]), "=r"(r[3]) : "r"(saddr));
}

__device__ __forceinline__ void ldsm4t(uint32_t r[4], uint32_t saddr) {
    asm volatile("ldmatrix.sync.aligned.m8n8.x4.trans.shared.b16 {%0,%1,%2,%3},[%4];"
                 : "=r"(r[0]), "=r"(r[1]), "=r"(r[2]), "=r"(r[3]) : "r"(saddr));
}

__device__ __forceinline__ uint32_t packh(__half a, __half b) {
    __half2 t; t.x = a; t.y = b;
    return *reinterpret_cast<uint32_t*>(&t);
}

__device__ __forceinline__ void cpa16(uint32_t dst, const void* src) {
    asm volatile("cp.async.cg.shared.global [%0], [%1], 16;" :: "r"(dst), "l"(src));
}
__device__ __forceinline__ void cpa_commit() { asm volatile("cp.async.commit_group;"); }
template<int N> __device__ __forceinline__ void cpa_wait() {
    asm volatile("cp.async.wait_group %0;" :: "n"(N));
}

// SW128-swizzled byte offset within a plane of 128-B rows.
__device__ __forceinline__ uint32_t swo(int row, uint32_t col) {
    return ((uint32_t)row << 7) + (col ^ (((uint32_t)row & 7u) << 4));
}

// ============================================================================
// Prep: weights, all hi-only fp16.
// ============================================================================
__global__ void split_w_kernel(const float* __restrict__ Wq, const float* __restrict__ Wk,
                               const float* __restrict__ Wv, const float* __restrict__ Wo) {
    int np = 589824 / 2;
    for (int i = blockIdx.x * blockDim.x + threadIdx.x; i < np;
         i += gridDim.x * blockDim.x) {
        float2 v = ((const float2*)Wo)[i];
        ((uint32_t*)g_woh)[i] = packh(__float2half(v.x), __float2half(v.y));
        if (i < 24576) {
            float2 q = ((const float2*)Wq)[i];
            ((uint32_t*)g_wqh)[i] = packh(__float2half(q.x), __float2half(q.y));
            float2 k = ((const float2*)Wk)[i];
            ((uint32_t*)g_wkh)[i] = packh(__float2half(k.x), __float2half(k.y));
            float2 w = ((const float2*)Wv)[i];
            ((uint32_t*)g_wvh)[i] = packh(__float2half(w.x), __float2half(w.y));
        }
    }
}

// ============================================================================
// Kernel A: fused QKV projection + attention, fp16, SW128 unpadded planes.
// Planes (8192 B): 0=x 1=Wq 2=Wk->V 3=Q->P 4=K 5=Wv. Sc aliases planes 0-1.
// Phases: stage | QK (cache x frags) | scores+V merged | softmax | PV.
// ============================================================================
#define PLB   8192
#define SMEMB (6 * PLB)                // 49152 B -> 4 CTAs/SM
#define SCST  65

__device__ __forceinline__ void gemm_pass(float acc[2][4][4], uint32_t aBase,
                                          uint32_t bBase, int mbase, int nbase,
                                          int lane) {
    const int r16 = lane & 15;
    const uint32_t kaq = (lane >> 4) * 16;
    #pragma unroll
    for (int kc = 0; kc < 4; ++kc) {
        uint32_t ka = kaq + kc * 32;
        uint32_t a0[4], a1[4], b0[4], b1[4];
        uint32_t a0a = aBase + swo(mbase + r16, ka);
        uint32_t b0a = bBase + swo(nbase + r16, ka);
        ldsm4(a0, a0a);
        ldsm4(a1, a0a + 2048);
        ldsm4(b0, b0a);
        ldsm4(b1, b0a + 2048);
        mma_f16(acc[0][0], a0, b0[0], b0[2]);
        mma_f16(acc[0][1], a0, b0[1], b0[3]);
        mma_f16(acc[0][2], a0, b1[0], b1[2]);
        mma_f16(acc[0][3], a0, b1[1], b1[3]);
        mma_f16(acc[1][0], a1, b0[0], b0[2]);
        mma_f16(acc[1][1], a1, b0[1], b0[3]);
        mma_f16(acc[1][2], a1, b1[0], b1[2]);
        mma_f16(acc[1][3], a1, b1[1], b1[3]);
    }
}

// A row-major, B row-major [k][n] via ldmatrix.trans (for P @ V)
__device__ __forceinline__ void gemm_pass_tb(float acc[2][4][4], uint32_t aBase,
                                             uint32_t bBase, int mbase, int nbase,
                                             int lane) {
    const int r16 = lane & 15;
    const uint32_t kaq = (lane >> 4) * 16;
    const int krow = ((lane >> 4) << 3) + (lane & 7);
    const int nch = ((lane >> 3) & 1) * 8;
    #pragma unroll
    for (int kc = 0; kc < 4; ++kc) {
        uint32_t ka = kaq + kc * 32;
        uint32_t a0[4], a1[4], b0[4], b1[4];
        uint32_t a0a = aBase + swo(mbase + r16, ka);
        ldsm4(a0, a0a);
        ldsm4(a1, a0a + 2048);
        const int rowB = kc * 16 + krow;
        ldsm4t(b0, bBase + swo(rowB, (nbase + nch) * 2));
        ldsm4t(b1, bBase + swo(rowB, (nbase + 16 + nch) * 2));
        mma_f16(acc[0][0], a0, b0[0], b0[2]);
        mma_f16(acc[0][1], a0, b0[1], b0[3]);
        mma_f16(acc[0][2], a0, b1[0], b1[2]);
        mma_f16(acc[0][3], a0, b1[1], b1[3]);
        mma_f16(acc[1][0], a1, b0[0], b0[2]);
        mma_f16(acc[1][1], a1, b0[1], b0[3]);
        mma_f16(acc[1][2], a1, b1[0], b1[2]);
        mma_f16(acc[1][3], a1, b1[1], b1[3]);
    }
}

__global__ void __launch_bounds__(128, 4)
attn_kernel(const float* __restrict__ x)
{
    extern __shared__ char smc[];
    float* Sc = (float*)smc;               // fp32 scores, aliases planes 0-1

    const int tid = threadIdx.x, lane = tid & 31, wid = tid >> 5;
    const int warp_m = wid >> 1, warp_n = wid & 1;
    const int mbase = warp_m * 32, nbase = warp_n * 32;
    const int lr = lane >> 2, lc = lane & 3;

    const int h = blockIdx.x % NHEADS;
    const int n = blockIdx.x / NHEADS;
    const int b = n >> 6, hb = (n >> 3) & 7, wb = n & 7;

    const uint32_t sb = (uint32_t)__cvta_generic_to_shared(smc);
    const uint32_t sX = sb, sWQ = sb + PLB, sWK = sb + 2 * PLB;
    const uint32_t sV = sb + 2 * PLB;      // V overwrites Wk
    const uint32_t sQ = sb + 3 * PLB;      // Q, later P
    const uint32_t sK = sb + 4 * PLB;
    const uint32_t sWV = sb + 5 * PLB;

    // ---- cp.async weights at entry (Wq->1, Wk->2, Wv->5), swizzled ----
    for (int q = tid; q < 1536; q += 128) {
        int pl = q >> 9;
        int rem = q & 511, e = rem >> 3, ch = rem & 7;
        const __half* src = (pl == 0 ? g_wqh : pl == 1 ? g_wkh : g_wvh)
                            + h * 4096 + e * 64 + ch * 8;
        uint32_t plane = (pl == 0) ? 1u : (pl == 1) ? 2u : 5u;
        cpa16(sb + plane * PLB + swo(e, ch * 16), src);
    }
    cpa_commit();

    // ---- stage x: fp32 loads -> fp16, swizzled; pad rows zero ----
    for (int q = tid; q < 512; q += 128) {
        int l = q >> 3, ch = q & 7;
        uint4 hv = make_uint4(0, 0, 0, 0);
        if (l < LW) {
            int i = l / 7, j = l - i * 7;
            const float* src = x + (((size_t)(b * 56 + hb * 7 + i)) * 56 + (wb * 7 + j)) * CCH
                               + h * DH + ch * 8;
            float4 f0 = *(const float4*)src;
            float4 f1 = *(const float4*)(src + 4);
            hv.x = packh(__float2half(f0.x), __float2half(f0.y));
            hv.y = packh(__float2half(f0.z), __float2half(f0.w));
            hv.z = packh(__float2half(f1.x), __float2half(f1.y));
            hv.w = packh(__float2half(f1.z), __float2half(f1.w));
        }
        *(uint4*)(smc + swo(l, ch * 16)) = hv;
    }
    cpa_wait<0>();
    __syncthreads();                        // barrier 1

    // ---- merged Q & K projections; CACHE x A-fragments in registers ----
    uint32_t axc[4][2][4];
    {
        float aq[2][4][4] = {}, ak[2][4][4] = {};
        const int r16 = lane & 15;
        const uint32_t kaq = (lane >> 4) * 16;
        #pragma unroll
        for (int kc = 0; kc < 4; ++kc) {
            uint32_t ka = kaq + kc * 32;
            uint32_t bq0[4], bq1[4], bk0[4], bk1[4];
            uint32_t a0a = sX + swo(mbase + r16, ka);
            uint32_t q0a = sWQ + swo(nbase + r16, ka);
            uint32_t k0a = sWK + swo(nbase + r16, ka);
            ldsm4(axc[kc][0], a0a); ldsm4(axc[kc][1], a0a + 2048);
            ldsm4(bq0, q0a); ldsm4(bq1, q0a + 2048);
            ldsm4(bk0, k0a); ldsm4(bk1, k0a + 2048);
            mma_f16(aq[0][0], axc[kc][0], bq0[0], bq0[2]);
            mma_f16(aq[0][1], axc[kc][0], bq0[1], bq0[3]);
            mma_f16(aq[0][2], axc[kc][0], bq1[0], bq1[2]);
            mma_f16(aq[0][3], axc[kc][0], bq1[1], bq1[3]);
            mma_f16(aq[1][0], axc[kc][1], bq0[0], bq0[2]);
            mma_f16(aq[1][1], axc[kc][1], bq0[1], bq0[3]);
            mma_f16(aq[1][2], axc[kc][1], bq1[0], bq1[2]);
            mma_f16(aq[1][3], axc[kc][1], bq1[1], bq1[3]);
            mma_f16(ak[0][0], axc[kc][0], bk0[0], bk0[2]);
            mma_f16(ak[0][1], axc[kc][0], bk0[1], bk0[3]);
            mma_f16(ak[0][2], axc[kc][0], bk1[0], bk1[2]);
            mma_f16(ak[0][3], axc[kc][0], bk1[1], bk1[3]);
            mma_f16(ak[1][0], axc[kc][1], bk0[0], bk0[2]);
            mma_f16(ak[1][1], axc[kc][1], bk0[1], bk0[3]);
            mma_f16(ak[1][2], axc[kc][1], bk1[0], bk1[2]);
            mma_f16(ak[1][3], axc[kc][1], bk1[1], bk1[3]);
        }
        #pragma unroll
        for (int f = 0; f < 2; ++f)
            #pragma unroll
            for (int g = 0; g < 4; ++g) {
                int r = mbase + 16 * f + lr;
                uint32_t off = swo(r, (uint32_t)(nbase + 8 * g + 2 * lc) * 2);
                *(uint32_t*)(smc + 3 * PLB + off) =
                    packh(__float2half(aq[f][g][0]), __float2half(aq[f][g][1]));
                *(uint32_t*)(smc + 3 * PLB + off + 1024) =
                    packh(__float2half(aq[f][g][2]), __float2half(aq[f][g][3]));
                *(uint32_t*)(smc + 4 * PLB + off) =
                    packh(__float2half(ak[f][g][0]), __float2half(ak[f][g][1]));
                *(uint32_t*)(smc + 4 * PLB + off + 1024) =
                    packh(__float2half(ak[f][g][2]), __float2half(ak[f][g][3]));
            }
    }
    __syncthreads();                        // barrier 2 (Wq/Wk dead, x via regs)

    // ---- MERGED phase: scores (Q@K^T -> Sc over x planes) + V (cached x) ----
    {
        // scores
        float acc[2][4][4] = {};
        gemm_pass(acc, sQ, sK, mbase, nbase, lane);
        #pragma unroll
        for (int f = 0; f < 2; ++f)
            #pragma unroll
            for (int g = 0; g < 4; ++g) {
                int r = mbase + 16 * f + lr;
                int c = nbase + 8 * g + 2 * lc;
                if (r < LW) {
                    Sc[r * SCST + c]     = acc[f][g][0] * 0.125f;
                    Sc[r * SCST + c + 1] = acc[f][g][1] * 0.125f;
                }
                if (r + 8 < LW) {
                    Sc[(r + 8) * SCST + c]     = acc[f][g][2] * 0.125f;
                    Sc[(r + 8) * SCST + c + 1] = acc[f][g][3] * 0.125f;
                }
            }
    }
    {
        // V = x @ Wv using cached A-fragments (no x plane reads)
        float acc[2][4][4] = {};
        const int r16 = lane & 15;
        const uint32_t kaq = (lane >> 4) * 16;
        #pragma unroll
        for (int kc = 0; kc < 4; ++kc) {
            uint32_t ka = kaq + kc * 32;
            uint32_t b0[4], b1[4];
            uint32_t b0a = sWV + swo(nbase + r16, ka);
            ldsm4(b0, b0a);
            ldsm4(b1, b0a + 2048);
            mma_f16(acc[0][0], axc[kc][0], b0[0], b0[2]);
            mma_f16(acc[0][1], axc[kc][0], b0[1], b0[3]);
            mma_f16(acc[0][2], axc[kc][0], b1[0], b1[2]);
            mma_f16(acc[0][3], axc[kc][0], b1[1], b1[3]);
            mma_f16(acc[1][0], axc[kc][1], b0[0], b0[2]);
            mma_f16(acc[1][1], axc[kc][1], b0[1], b0[3]);
            mma_f16(acc[1][2], axc[kc][1], b1[0], b1[2]);
            mma_f16(acc[1][3], axc[kc][1], b1[1], b1[3]);
        }
        #pragma unroll
        for (int f = 0; f < 2; ++f)
            #pragma unroll
            for (int g = 0; g < 4; ++g) {
                int r = mbase + 16 * f + lr;
                uint32_t off = swo(r, (uint32_t)(nbase + 8 * g + 2 * lc) * 2);
                *(uint32_t*)(smc + 2 * PLB + off) =
                    packh(__float2half(acc[f][g][0]), __float2half(acc[f][g][1]));
                *(uint32_t*)(smc + 2 * PLB + off + 1024) =
                    packh(__float2half(acc[f][g][2]), __float2half(acc[f][g][3]));
            }
    }
    __syncthreads();                        // barrier 3

    // ---- softmax: 2 threads per row, write P into plane 3 (over Q) ----
    if (tid < 2 * LW) {
        const int r = tid >> 1, half = tid & 1;
        const unsigned msk = (tid < 96) ? 0xFFFFFFFFu : 0x3u;
        float* row = Sc + r * SCST;
        const int m0 = half ? 25 : 0, m1 = half ? LW : 25;
        float mx = -1e30f;
        #pragma unroll
        for (int m = m0; m < m1; ++m) mx = fmaxf(mx, row[m]);
        mx = fmaxf(mx, __shfl_xor_sync(msk, mx, 1));
        float s = 0.f;
        #pragma unroll
        for (int m = m0; m < m1; ++m) { float e = __expf(row[m] - mx); row[m] = e; s += e; }
        s += __shfl_xor_sync(msk, s, 1);
        float inv = 1.f / s;
        __syncwarp(msk);
        #pragma unroll
        for (int mw = half * 16; mw < half * 16 + 16; ++mw) {
            int mc = 2 * mw;
            float p0 = (mc     < LW) ? row[mc] * inv     : 0.f;
            float p1 = (mc + 1 < LW) ? row[mc + 1] * inv : 0.f;
            *(uint32_t*)(smc + 3 * PLB + swo(r, (uint32_t)mw * 4)) =
                packh(__float2half(p0), __float2half(p1));
        }
    }
    __syncthreads();                        // barrier 4

    // ---- out = P @ V (trans-B ldsm), store fp16 to g_sh ----
    {
        float acc[2][4][4] = {};
        gemm_pass_tb(acc, sQ, sV, mbase, nbase, lane);
        #pragma unroll
        for (int f = 0; f < 2; ++f)
            #pragma unroll
            for (int g = 0; g < 4; ++g) {
                int r = mbase + 16 * f + lr;
                int c = nbase + 8 * g + 2 * lc;
                if (r < LW) {
                    size_t off = ((size_t)n * LW + r) * CCH + h * DH + c;
                    *(uint32_t*)(g_sh + off) =
                        packh(__float2half(acc[f][g][0]), __float2half(acc[f][g][1]));
                }
                if (r + 8 < LW) {
                    size_t off = ((size_t)n * LW + r + 8) * CCH + h * DH + c;
                    *(uint32_t*)(g_sh + off) =
                        packh(__float2half(acc[f][g][2]), __float2half(acc[f][g][3]));
                }
            }
    }
}

// ============================================================================
// Kernel B: y = S @ Wo^T + bo, pure fp16 GEMM. CTA tile 128x128, warp 32x64,
// BK=64, SW128 rows, 3-stage cp.async pipeline, 256 threads, 2 CTAs/SM.
// ============================================================================
#define PSTG 32768                     // A 16384 + B 16384
#define QA   0
#define QB   16384
#define PROJ_SMEM (3 * PSTG)           // 98304 B

__device__ __forceinline__ void proj_stage(uint32_t sb, int s, int kt,
                                           int m_base, int n_base, int tid) {
    const uint32_t base = sb + s * PSTG;
    #pragma unroll
    for (int c = tid; c < 1024; c += 256) {        // A: 128 rows x 8 chunks
        int row = c >> 3, ch = c & 7;
        cpa16(base + QA + swo(row, ch * 16),
              g_sh + (size_t)(m_base + row) * CCH + kt + ch * 8);
    }
    #pragma unroll
    for (int c = tid; c < 1024; c += 256) {        // B: 128 rows x 8 chunks
        int row = c >> 3, ch = c & 7;
        cpa16(base + QB + swo(row, ch * 16),
              g_woh + (size_t)(n_base + row) * CCH + kt + ch * 8);
    }
    cpa_commit();
}

__global__ void __launch_bounds__(256, 2)
proj_kernel(const float* __restrict__ bo, float* __restrict__ y)
{
    extern __shared__ char psm[];
    const int tid = threadIdx.x, lane = tid & 31, wid = tid >> 5;
    const int warp_m = wid >> 1, warp_n = wid & 1;      // 4 x 2 warps
    const int lr = lane >> 2, lc = lane & 3;
    const int n_base = (blockIdx.x % 6) * 128;
    const int m_base = (blockIdx.x / 6) * 128;
    const uint32_t sb = (uint32_t)__cvta_generic_to_shared(psm);
    const int r16 = lane & 15;
    const uint32_t kaq = (lane >> 4) * 16;

    float acc[2][8][4] = {};

    auto compute = [&](int s) {
        const uint32_t aB = sb + s * PSTG + QA;
        const uint32_t bB = sb + s * PSTG + QB;
        #pragma unroll
        for (int kc = 0; kc < 4; ++kc) {
            uint32_t ka = kaq + kc * 32;
            uint32_t a0[4], a1[4], bf[4][4];
            uint32_t a0a = aB + swo(warp_m * 32 + r16, ka);
            ldsm4(a0, a0a);
            ldsm4(a1, a0a + 2048);
            #pragma unroll
            for (int nn = 0; nn < 4; ++nn)
                ldsm4(bf[nn], bB + swo(warp_n * 64 + nn * 16 + r16, ka));
            #pragma unroll
            for (int nn = 0; nn < 4; ++nn) {
                mma_f16(acc[0][2 * nn],     a0, bf[nn][0], bf[nn][2]);
                mma_f16(acc[0][2 * nn + 1], a0, bf[nn][1], bf[nn][3]);
                mma_f16(acc[1][2 * nn],     a1, bf[nn][0], bf[nn][2]);
                mma_f16(acc[1][2 * nn + 1], a1, bf[nn][1], bf[nn][3]);
            }
        }
    };

    proj_stage(sb, 0, 0, m_base, n_base, tid);
    proj_stage(sb, 1, 64, m_base, n_base, tid);
    #pragma unroll 1
    for (int t = 0; t < 12; ++t) {
        if (t < 11) cpa_wait<1>(); else cpa_wait<0>();
        __syncthreads();
        compute(t % 3);
        if (t + 2 < 12) proj_stage(sb, (t + 2) % 3, (t + 2) * 64, m_base, n_base, tid);
    }

    #pragma unroll
    for (int g = 0; g < 8; ++g) {
        int c = n_base + warp_n * 64 + 8 * g + 2 * lc;
        float b0 = bo[c], b1 = bo[c + 1];
        #pragma unroll
        for (int f = 0; f < 2; ++f) {
            int r = m_base + warp_m * 32 + 16 * f + lr;
            *(float2*)&y[(size_t)r * CCH + c] =
                make_float2(acc[f][g][0] + b0, acc[f][g][1] + b1);
            *(float2*)&y[(size_t)(r + 8) * CCH + c] =
                make_float2(acc[f][g][2] + b0, acc[f][g][3] + b1);
        }
    }
}

// ============================================================================
extern "C" void kernel_launch(void* const* d_in, const int* in_sizes, int n_in,
                              void* d_out, int out_size)
{
    const float* x  = (const float*)d_in[0];
    const float* Wq = (const float*)d_in[1];
    const float* Wk = (const float*)d_in[2];
    const float* Wv = (const float*)d_in[3];
    const float* Wo = (const float*)d_in[4];
    const float* bo = (const float*)d_in[5];
    float* y = (float*)d_out;

    cudaFuncSetAttribute(attn_kernel, cudaFuncAttributeMaxDynamicSharedMemorySize, SMEMB);
    cudaFuncSetAttribute(proj_kernel, cudaFuncAttributeMaxDynamicSharedMemorySize, PROJ_SMEM);

    split_w_kernel<<<576, 256>>>(Wq, Wk, Wv, Wo);
    attn_kernel<<<NWIN * NHEADS, 128, SMEMB>>>(x);
    proj_kernel<<<784 * 6, 256, PROJ_SMEM>>>(bo, y);
}